// round 1
// baseline (speedup 1.0000x reference)
#include <cuda_runtime.h>
#include <cuda_bf16.h>

// Problem constants (fixed shapes from reference)
#define BB 4
#define TT 2048
#define DD 1024
#define HH 16
#define HD 64
#define MM (BB * TT)   // 8192

// Scratch: g_buf[0]=Q, g_buf[1]=K, g_buf[2]=V, g_buf[3]=attn-out   (each [B,T,D] fp32)
__device__ float g_buf[4][(size_t)MM * DD];

// ---------------------------------------------------------------------------
// NT GEMM: C[m,n] = sum_k A[m,k] * W[n,k] (+bias[n])
// A: [M,K] row-major, W: [N,K] row-major (torch Linear weight), C: [M,N]
// Tiles: 128x128, K-step 8, 256 threads, 8x8 per-thread register tile.
// ---------------------------------------------------------------------------
__global__ __launch_bounds__(256, 2)
void gemm_nt_kernel(const float* __restrict__ Aopt, int aIdx,
                    const float* __restrict__ W,
                    const float* __restrict__ bias,
                    float* __restrict__ Copt, int cIdx,
                    int M, int N, int K)
{
    const float* A = Aopt ? Aopt : g_buf[aIdx];
    float*       C = Copt ? Copt : g_buf[cIdx];

    __shared__ float As[8][132];
    __shared__ float Bs[8][132];

    const int tid = threadIdx.x;
    const int tx = tid & 15;          // 0..15 (n direction)
    const int ty = tid >> 4;          // 0..15 (m direction)
    const int m0 = blockIdx.y * 128;
    const int n0 = blockIdx.x * 128;

    const int lr = tid >> 1;          // 0..127 tile row for loads
    const int lc = (tid & 1) * 4;     // 0 or 4

    const float* Aptr = A + (size_t)(m0 + lr) * K + lc;
    const float* Wptr = W + (size_t)(n0 + lr) * K + lc;

    float acc[8][8];
#pragma unroll
    for (int i = 0; i < 8; ++i)
#pragma unroll
        for (int j = 0; j < 8; ++j) acc[i][j] = 0.f;

    for (int k0 = 0; k0 < K; k0 += 8) {
        float4 av = *(const float4*)(Aptr + k0);
        float4 wv = *(const float4*)(Wptr + k0);
        As[lc + 0][lr] = av.x; As[lc + 1][lr] = av.y;
        As[lc + 2][lr] = av.z; As[lc + 3][lr] = av.w;
        Bs[lc + 0][lr] = wv.x; Bs[lc + 1][lr] = wv.y;
        Bs[lc + 2][lr] = wv.z; Bs[lc + 3][lr] = wv.w;
        __syncthreads();

#pragma unroll
        for (int kk = 0; kk < 8; ++kk) {
            float a[8], b[8];
#pragma unroll
            for (int i = 0; i < 8; ++i) a[i] = As[kk][ty * 8 + i];
#pragma unroll
            for (int j = 0; j < 8; ++j) b[j] = Bs[kk][tx * 8 + j];
#pragma unroll
            for (int i = 0; i < 8; ++i)
#pragma unroll
                for (int j = 0; j < 8; ++j)
                    acc[i][j] += a[i] * b[j];
        }
        __syncthreads();
    }

#pragma unroll
    for (int i = 0; i < 8; ++i) {
        const size_t m = (size_t)(m0 + ty * 8 + i);
#pragma unroll
        for (int j = 0; j < 8; ++j) {
            const int n = n0 + tx * 8 + j;
            float r = acc[i][j];
            if (bias) r += bias[n];
            C[m * N + n] = r;
        }
    }
}

// ---------------------------------------------------------------------------
// Causal flash attention. One block = 128 query rows of one (b,h).
// Each thread owns one query row: q[64] + O[64] in registers.
// K/V tiles (64 keys x 64 dims) staged through shared memory.
// Online softmax: stale-max within tile, rescale once per tile.
// Q,K,V,O all in [B,T,D] layout (head h = channel slice h*64..h*64+63).
// ---------------------------------------------------------------------------
__global__ __launch_bounds__(128, 3)
void flash_attn_kernel()
{
    const int qb = blockIdx.x;       // 0..15
    const int h  = blockIdx.y;       // 0..15
    const int b  = blockIdx.z;       // 0..3
    const int tid = threadIdx.x;     // 0..127

    extern __shared__ float sm[];    // max(128*65, 2*64*64) floats = 8320

    const int q0 = qb * 128;
    const int qi = q0 + tid;
    const size_t baseQ = ((size_t)(b * TT + q0)) * DD + h * HD;

    // Stage Q tile coalesced: [128][65] padded
#pragma unroll
    for (int i = 0; i < 16; ++i) {
        int lin = tid + i * 128;             // float4 index, 2048 total
        int row = lin >> 4;
        int c4  = (lin & 15) * 4;
        float4 v4 = *(const float4*)&g_buf[0][baseQ + (size_t)row * DD + c4];
        float* dst = &sm[row * 65 + c4];
        dst[0] = v4.x; dst[1] = v4.y; dst[2] = v4.z; dst[3] = v4.w;
    }
    __syncthreads();

    float q[HD];
#pragma unroll
    for (int d = 0; d < HD; ++d) q[d] = sm[tid * 65 + d] * 0.125f; // scale = HD^-0.5
    __syncthreads();

    float* Ks = sm;                 // [64][64]
    float* Vs = sm + 64 * 64;       // [64][64]

    float O[HD];
#pragma unroll
    for (int d = 0; d < HD; ++d) O[d] = 0.f;
    float mrun = 0.f;               // logits are bounded (|s| << 10), 0 is safe
    float lsum = 0.f;

    const int nkeys = q0 + 128;     // max key this block needs (exclusive)
    for (int kt = 0; kt < nkeys; kt += 64) {
        // stage K,V tile (64 rows x 64 cols), coalesced
        const size_t baseK = ((size_t)(b * TT + kt)) * DD + h * HD;
#pragma unroll
        for (int i = 0; i < 8; ++i) {
            int lin = tid + i * 128;        // 1024 float4 per operand
            int row = lin >> 4;
            int c4  = (lin & 15) * 4;
            size_t g = baseK + (size_t)row * DD + c4;
            *(float4*)&Ks[row * 64 + c4] = *(const float4*)&g_buf[1][g];
            *(float4*)&Vs[row * 64 + c4] = *(const float4*)&g_buf[2][g];
        }
        __syncthreads();

        if (kt <= qi) {
            const int jmax = min(64, qi - kt + 1);   // causal bound
            float tm = mrun;
            for (int j = 0; j < jmax; ++j) {
                const float* kr = &Ks[j * 64];
                float s0 = 0.f, s1 = 0.f, s2 = 0.f, s3 = 0.f;
#pragma unroll
                for (int d = 0; d < HD; d += 4) {
                    s0 += q[d + 0] * kr[d + 0];
                    s1 += q[d + 1] * kr[d + 1];
                    s2 += q[d + 2] * kr[d + 2];
                    s3 += q[d + 3] * kr[d + 3];
                }
                float s = (s0 + s1) + (s2 + s3);
                tm = fmaxf(tm, s);
                float p = __expf(s - mrun);          // stale max: safe, logits bounded
                lsum += p;
                const float* vr = &Vs[j * 64];
#pragma unroll
                for (int d = 0; d < HD; ++d) O[d] += p * vr[d];
            }
            if (tm > mrun) {
                float c = __expf(mrun - tm);
                lsum *= c;
#pragma unroll
                for (int d = 0; d < HD; ++d) O[d] *= c;
                mrun = tm;
            }
        }
        __syncthreads();
    }

    const float inv = 1.f / lsum;
    const size_t baseO = ((size_t)(b * TT + qi)) * DD + h * HD;
#pragma unroll
    for (int d = 0; d < HD; ++d)
        g_buf[3][baseO + d] = O[d] * inv;
}

// ---------------------------------------------------------------------------
// Launch: inputs per metadata order: x, Wk, Wq, Wv, Wp, bp
// ---------------------------------------------------------------------------
extern "C" void kernel_launch(void* const* d_in, const int* in_sizes, int n_in,
                              void* d_out, int out_size)
{
    const float* x  = (const float*)d_in[0];
    const float* Wk = (const float*)d_in[1];
    const float* Wq = (const float*)d_in[2];
    const float* Wv = (const float*)d_in[3];
    const float* Wp = (const float*)d_in[4];
    const float* bp = (const float*)d_in[5];
    float* out = (float*)d_out;

    dim3 gGrid(DD / 128, MM / 128);   // 8 x 64
    dim3 gBlk(256);

    // Q, K, V projections (NT GEMMs) into g_buf[0..2]
    gemm_nt_kernel<<<gGrid, gBlk>>>(x, 0, Wq, nullptr, nullptr, 0, MM, DD, DD);
    gemm_nt_kernel<<<gGrid, gBlk>>>(x, 0, Wk, nullptr, nullptr, 1, MM, DD, DD);
    gemm_nt_kernel<<<gGrid, gBlk>>>(x, 0, Wv, nullptr, nullptr, 2, MM, DD, DD);

    // Causal flash attention into g_buf[3]
    dim3 fGrid(TT / 128, HH, BB);     // 16 x 16 x 4
    size_t fSmem = 128 * 65 * sizeof(float);   // 33280 B (>= 2*64*64*4)
    flash_attn_kernel<<<fGrid, 128, fSmem>>>();

    // Output projection with bias -> d_out
    gemm_nt_kernel<<<gGrid, gBlk>>>(nullptr, 3, Wp, bp, out, 0, MM, DD, DD);
}

// round 2
// speedup vs baseline: 1.3096x; 1.3096x over previous
#include <cuda_runtime.h>
#include <cuda_bf16.h>
#include <cstdint>

// Problem constants (fixed shapes from reference)
#define BB 4
#define TT 2048
#define DD 1024
#define HH 16
#define HD 64
#define MM (BB * TT)   // 8192

// fp32 scratch: g_buf[0]=Q, g_buf[1]=K, g_buf[2]=V, g_buf[3]=attn-out
__device__ float g_buf[4][(size_t)MM * DD];

// split-bf16 operands (hi/lo) for tensor-core GEMMs
__device__ __align__(16) __nv_bfloat16 g_xh[(size_t)MM * DD];
__device__ __align__(16) __nv_bfloat16 g_xl[(size_t)MM * DD];
__device__ __align__(16) __nv_bfloat16 g_ah[(size_t)MM * DD];
__device__ __align__(16) __nv_bfloat16 g_al[(size_t)MM * DD];
__device__ __align__(16) __nv_bfloat16 g_wh[4][(size_t)DD * DD];
__device__ __align__(16) __nv_bfloat16 g_wl[4][(size_t)DD * DD];

// ---------------------------------------------------------------------------
// fp32 -> (bf16 hi, bf16 lo) split.  dsel: 0=x, 1=attn-out, 2..5=weights[0..3]
// src==nullptr -> read g_buf[3]
// ---------------------------------------------------------------------------
__global__ void split_fp32_bf16(const float* __restrict__ src, int dsel, int n4)
{
    int i = blockIdx.x * blockDim.x + threadIdx.x;
    if (i >= n4) return;
    const float4* s = (const float4*)(src ? src : g_buf[3]);
    float4 v = s[i];

    __nv_bfloat16 *H, *L;
    if (dsel == 0)      { H = g_xh; L = g_xl; }
    else if (dsel == 1) { H = g_ah; L = g_al; }
    else                { H = g_wh[dsel - 2]; L = g_wl[dsel - 2]; }

    __nv_bfloat16 h0 = __float2bfloat16(v.x);
    __nv_bfloat16 h1 = __float2bfloat16(v.y);
    __nv_bfloat16 h2 = __float2bfloat16(v.z);
    __nv_bfloat16 h3 = __float2bfloat16(v.w);
    __nv_bfloat16 l0 = __float2bfloat16(v.x - __bfloat162float(h0));
    __nv_bfloat16 l1 = __float2bfloat16(v.y - __bfloat162float(h1));
    __nv_bfloat16 l2 = __float2bfloat16(v.z - __bfloat162float(h2));
    __nv_bfloat16 l3 = __float2bfloat16(v.w - __bfloat162float(h3));

    *(__nv_bfloat162*)&H[4 * (size_t)i]     = __nv_bfloat162(h0, h1);
    *(__nv_bfloat162*)&H[4 * (size_t)i + 2] = __nv_bfloat162(h2, h3);
    *(__nv_bfloat162*)&L[4 * (size_t)i]     = __nv_bfloat162(l0, l1);
    *(__nv_bfloat162*)&L[4 * (size_t)i + 2] = __nv_bfloat162(l2, l3);
}

// ---------------------------------------------------------------------------
// Tensor-core NT GEMM, split-bf16 x3 passes, fp32 accumulate.
// C[m,n] = sum_k A[m,k]*W[n,k] (+bias).  Block 128x128, K-step 32, 256 thr.
// ---------------------------------------------------------------------------
#define BK 32
#define SST 40   // smem row stride in bf16 (conflict-free for ldmatrix)

__device__ __forceinline__ uint32_t smem_u32(const void* p) {
    return (uint32_t)__cvta_generic_to_shared(p);
}
__device__ __forceinline__ void ldm_x4(uint32_t addr, uint32_t* r) {
    asm volatile("ldmatrix.sync.aligned.m8n8.x4.shared.b16 {%0,%1,%2,%3}, [%4];"
                 : "=r"(r[0]), "=r"(r[1]), "=r"(r[2]), "=r"(r[3]) : "r"(addr));
}
__device__ __forceinline__ void mma_bf16(float* c, const uint32_t* a, uint32_t b0, uint32_t b1) {
    asm volatile("mma.sync.aligned.m16n8k16.row.col.f32.bf16.bf16.f32 "
                 "{%0,%1,%2,%3}, {%4,%5,%6,%7}, {%8,%9}, {%0,%1,%2,%3};"
                 : "+f"(c[0]), "+f"(c[1]), "+f"(c[2]), "+f"(c[3])
                 : "r"(a[0]), "r"(a[1]), "r"(a[2]), "r"(a[3]), "r"(b0), "r"(b1));
}

__global__ __launch_bounds__(256, 1)
void gemm_nt_tc(int aSel, int wSel, const float* __restrict__ bias,
                float* __restrict__ Cout, int cSel, int M, int N, int K)
{
    const __nv_bfloat16* Ah = aSel ? g_ah : g_xh;
    const __nv_bfloat16* Al = aSel ? g_al : g_xl;
    const __nv_bfloat16* Wh = g_wh[wSel];
    const __nv_bfloat16* Wl = g_wl[wSel];
    float* C = Cout ? Cout : g_buf[cSel];

    __shared__ __nv_bfloat16 sm[4][128 * SST];   // Ah, Al, Wh, Wl tiles

    const int tid  = threadIdx.x;
    const int warp = tid >> 5, lane = tid & 31;
    const int wm = warp >> 1, wn = warp & 1;     // 4 x 2 warp grid
    const int m0 = blockIdx.y * 128, n0 = blockIdx.x * 128;

    // gmem->smem load mapping: each thread loads 16 contiguous bf16 per matrix
    const int lrow = tid >> 1;
    const int lcol = (tid & 1) * 16;
    const size_t gA = (size_t)(m0 + lrow) * K + lcol;
    const size_t gW = (size_t)(n0 + lrow) * K + lcol;
    const int sdst = lrow * SST + lcol;

    float acc[2][8][4];
#pragma unroll
    for (int i = 0; i < 2; ++i)
#pragma unroll
        for (int j = 0; j < 8; ++j)
#pragma unroll
            for (int t = 0; t < 4; ++t) acc[i][j][t] = 0.f;

    for (int k0 = 0; k0 < K; k0 += BK) {
        const int4* pAh = (const int4*)(Ah + gA + k0);
        const int4* pAl = (const int4*)(Al + gA + k0);
        const int4* pWh = (const int4*)(Wh + gW + k0);
        const int4* pWl = (const int4*)(Wl + gW + k0);
        *(int4*)&sm[0][sdst] = pAh[0];  *(int4*)&sm[0][sdst + 8] = pAh[1];
        *(int4*)&sm[1][sdst] = pAl[0];  *(int4*)&sm[1][sdst + 8] = pAl[1];
        *(int4*)&sm[2][sdst] = pWh[0];  *(int4*)&sm[2][sdst + 8] = pWh[1];
        *(int4*)&sm[3][sdst] = pWl[0];  *(int4*)&sm[3][sdst + 8] = pWl[1];
        __syncthreads();

#pragma unroll
        for (int ks = 0; ks < BK; ks += 16) {
            uint32_t aH[2][4], aL[2][4], bH[4][4], bL[4][4];

            const int arow = wm * 32 + (lane & 15);
            const int acol = ks + ((lane >> 4) << 3);
#pragma unroll
            for (int mt = 0; mt < 2; ++mt) {
                ldm_x4(smem_u32(&sm[0][(arow + mt * 16) * SST + acol]), aH[mt]);
                ldm_x4(smem_u32(&sm[1][(arow + mt * 16) * SST + acol]), aL[mt]);
            }
            const int brow = wn * 64 + ((lane >> 4) << 3) + (lane & 7);
            const int bcol = ks + ((lane >> 3) & 1) * 8;
#pragma unroll
            for (int nn = 0; nn < 4; ++nn) {
                ldm_x4(smem_u32(&sm[2][(brow + nn * 16) * SST + bcol]), bH[nn]);
                ldm_x4(smem_u32(&sm[3][(brow + nn * 16) * SST + bcol]), bL[nn]);
            }

#pragma unroll
            for (int mt = 0; mt < 2; ++mt)
#pragma unroll
                for (int nt = 0; nt < 8; ++nt) {
                    const int p = nt >> 1, q = (nt & 1) * 2;
                    mma_bf16(acc[mt][nt], aH[mt], bH[p][q], bH[p][q + 1]);  // hi*hi
                    mma_bf16(acc[mt][nt], aH[mt], bL[p][q], bL[p][q + 1]);  // hi*lo
                    mma_bf16(acc[mt][nt], aL[mt], bH[p][q], bH[p][q + 1]);  // lo*hi
                }
        }
        __syncthreads();
    }

    // epilogue
#pragma unroll
    for (int mt = 0; mt < 2; ++mt) {
#pragma unroll
        for (int nt = 0; nt < 8; ++nt) {
            const int m = m0 + wm * 32 + mt * 16 + (lane >> 2);
            const int n = n0 + wn * 64 + nt * 8 + (lane & 3) * 2;
            float b0 = 0.f, b1 = 0.f;
            if (bias) { b0 = bias[n]; b1 = bias[n + 1]; }
            float2 v0 = make_float2(acc[mt][nt][0] + b0, acc[mt][nt][1] + b1);
            float2 v1 = make_float2(acc[mt][nt][2] + b0, acc[mt][nt][3] + b1);
            *(float2*)&C[(size_t)m * N + n]       = v0;
            *(float2*)&C[(size_t)(m + 8) * N + n] = v1;
        }
    }
}

// ---------------------------------------------------------------------------
// Causal flash attention (fp32, unchanged from R0). One block = 128 q rows.
// ---------------------------------------------------------------------------
__global__ __launch_bounds__(128, 3)
void flash_attn_kernel()
{
    const int qb = blockIdx.x;
    const int h  = blockIdx.y;
    const int b  = blockIdx.z;
    const int tid = threadIdx.x;

    extern __shared__ float smf[];

    const int q0 = qb * 128;
    const int qi = q0 + tid;
    const size_t baseQ = ((size_t)(b * TT + q0)) * DD + h * HD;

#pragma unroll
    for (int i = 0; i < 16; ++i) {
        int lin = tid + i * 128;
        int row = lin >> 4;
        int c4  = (lin & 15) * 4;
        float4 v4 = *(const float4*)&g_buf[0][baseQ + (size_t)row * DD + c4];
        float* dst = &smf[row * 65 + c4];
        dst[0] = v4.x; dst[1] = v4.y; dst[2] = v4.z; dst[3] = v4.w;
    }
    __syncthreads();

    float q[HD];
#pragma unroll
    for (int d = 0; d < HD; ++d) q[d] = smf[tid * 65 + d] * 0.125f;
    __syncthreads();

    float* Ks = smf;
    float* Vs = smf + 64 * 64;

    float O[HD];
#pragma unroll
    for (int d = 0; d < HD; ++d) O[d] = 0.f;
    float mrun = 0.f;
    float lsum = 0.f;

    const int nkeys = q0 + 128;
    for (int kt = 0; kt < nkeys; kt += 64) {
        const size_t baseK = ((size_t)(b * TT + kt)) * DD + h * HD;
#pragma unroll
        for (int i = 0; i < 8; ++i) {
            int lin = tid + i * 128;
            int row = lin >> 4;
            int c4  = (lin & 15) * 4;
            size_t g = baseK + (size_t)row * DD + c4;
            *(float4*)&Ks[row * 64 + c4] = *(const float4*)&g_buf[1][g];
            *(float4*)&Vs[row * 64 + c4] = *(const float4*)&g_buf[2][g];
        }
        __syncthreads();

        if (kt <= qi) {
            const int jmax = min(64, qi - kt + 1);
            float tm = mrun;
            for (int j = 0; j < jmax; ++j) {
                const float* kr = &Ks[j * 64];
                float s0 = 0.f, s1 = 0.f, s2 = 0.f, s3 = 0.f;
#pragma unroll
                for (int d = 0; d < HD; d += 4) {
                    s0 += q[d + 0] * kr[d + 0];
                    s1 += q[d + 1] * kr[d + 1];
                    s2 += q[d + 2] * kr[d + 2];
                    s3 += q[d + 3] * kr[d + 3];
                }
                float s = (s0 + s1) + (s2 + s3);
                tm = fmaxf(tm, s);
                float p = __expf(s - mrun);
                lsum += p;
                const float* vr = &Vs[j * 64];
#pragma unroll
                for (int d = 0; d < HD; ++d) O[d] += p * vr[d];
            }
            if (tm > mrun) {
                float c = __expf(mrun - tm);
                lsum *= c;
#pragma unroll
                for (int d = 0; d < HD; ++d) O[d] *= c;
                mrun = tm;
            }
        }
        __syncthreads();
    }

    const float inv = 1.f / lsum;
    const size_t baseO = ((size_t)(b * TT + qi)) * DD + h * HD;
#pragma unroll
    for (int d = 0; d < HD; ++d)
        g_buf[3][baseO + d] = O[d] * inv;
}

// ---------------------------------------------------------------------------
// Launch: inputs per metadata order: x, Wk, Wq, Wv, Wp, bp
// ---------------------------------------------------------------------------
extern "C" void kernel_launch(void* const* d_in, const int* in_sizes, int n_in,
                              void* d_out, int out_size)
{
    const float* x  = (const float*)d_in[0];
    const float* Wk = (const float*)d_in[1];
    const float* Wq = (const float*)d_in[2];
    const float* Wv = (const float*)d_in[3];
    const float* Wp = (const float*)d_in[4];
    const float* bp = (const float*)d_in[5];
    float* out = (float*)d_out;

    // split inputs into bf16 hi/lo
    {
        int n4 = MM * DD / 4;
        split_fp32_bf16<<<(n4 + 255) / 256, 256>>>(x, 0, n4);
        int w4 = DD * DD / 4;
        split_fp32_bf16<<<(w4 + 255) / 256, 256>>>(Wq, 2, w4);  // slot 0
        split_fp32_bf16<<<(w4 + 255) / 256, 256>>>(Wk, 3, w4);  // slot 1
        split_fp32_bf16<<<(w4 + 255) / 256, 256>>>(Wv, 4, w4);  // slot 2
        split_fp32_bf16<<<(w4 + 255) / 256, 256>>>(Wp, 5, w4);  // slot 3
    }

    dim3 gGrid(DD / 128, MM / 128);   // 8 x 64
    // Q, K, V projections
    gemm_nt_tc<<<gGrid, 256>>>(0, 0, nullptr, nullptr, 0, MM, DD, DD);
    gemm_nt_tc<<<gGrid, 256>>>(0, 1, nullptr, nullptr, 1, MM, DD, DD);
    gemm_nt_tc<<<gGrid, 256>>>(0, 2, nullptr, nullptr, 2, MM, DD, DD);

    // causal flash attention -> g_buf[3]
    dim3 fGrid(TT / 128, HH, BB);
    size_t fSmem = 128 * 65 * sizeof(float);
    flash_attn_kernel<<<fGrid, 128, fSmem>>>();

    // split attn-out, then output projection with bias -> d_out
    {
        int n4 = MM * DD / 4;
        split_fp32_bf16<<<(n4 + 255) / 256, 256>>>(nullptr, 1, n4);
    }
    gemm_nt_tc<<<gGrid, 256>>>(1, 3, bp, out, 0, MM, DD, DD);
}

// round 3
// speedup vs baseline: 2.5013x; 1.9100x over previous
#include <cuda_runtime.h>
#include <cuda_bf16.h>
#include <cstdint>

// Problem constants
#define BB 4
#define TT 2048
#define DD 1024
#define HH 16
#define HD 64
#define MM (BB * TT)   // 8192

// split-bf16 tensors (hi/lo pairs)
__device__ __align__(16) __nv_bfloat16 g_xh[(size_t)MM * DD];
__device__ __align__(16) __nv_bfloat16 g_xl[(size_t)MM * DD];
__device__ __align__(16) __nv_bfloat16 g_ah[(size_t)MM * DD];
__device__ __align__(16) __nv_bfloat16 g_al[(size_t)MM * DD];
__device__ __align__(16) __nv_bfloat16 g_qh[(size_t)MM * DD];
__device__ __align__(16) __nv_bfloat16 g_ql[(size_t)MM * DD];
__device__ __align__(16) __nv_bfloat16 g_kh[(size_t)MM * DD];
__device__ __align__(16) __nv_bfloat16 g_kl[(size_t)MM * DD];
__device__ __align__(16) __nv_bfloat16 g_vh[(size_t)MM * DD];
__device__ __align__(16) __nv_bfloat16 g_vl[(size_t)MM * DD];
__device__ __align__(16) __nv_bfloat16 g_wh[4][(size_t)DD * DD];  // Wq,Wk,Wv,Wp
__device__ __align__(16) __nv_bfloat16 g_wl[4][(size_t)DD * DD];

// ---------------------------------------------------------------------------
// fp32 -> (bf16 hi, bf16 lo) split.  dsel: 0=x, 2..5=weights[0..3]
// ---------------------------------------------------------------------------
__global__ void split_fp32_bf16(const float* __restrict__ src, int dsel, int n4)
{
    int i = blockIdx.x * blockDim.x + threadIdx.x;
    if (i >= n4) return;
    float4 v = ((const float4*)src)[i];

    __nv_bfloat16 *H, *L;
    if (dsel == 0) { H = g_xh; L = g_xl; }
    else           { H = g_wh[dsel - 2]; L = g_wl[dsel - 2]; }

    __nv_bfloat16 h0 = __float2bfloat16(v.x), h1 = __float2bfloat16(v.y);
    __nv_bfloat16 h2 = __float2bfloat16(v.z), h3 = __float2bfloat16(v.w);
    __nv_bfloat16 l0 = __float2bfloat16(v.x - __bfloat162float(h0));
    __nv_bfloat16 l1 = __float2bfloat16(v.y - __bfloat162float(h1));
    __nv_bfloat16 l2 = __float2bfloat16(v.z - __bfloat162float(h2));
    __nv_bfloat16 l3 = __float2bfloat16(v.w - __bfloat162float(h3));

    *(__nv_bfloat162*)&H[4 * (size_t)i]     = __nv_bfloat162(h0, h1);
    *(__nv_bfloat162*)&H[4 * (size_t)i + 2] = __nv_bfloat162(h2, h3);
    *(__nv_bfloat162*)&L[4 * (size_t)i]     = __nv_bfloat162(l0, l1);
    *(__nv_bfloat162*)&L[4 * (size_t)i + 2] = __nv_bfloat162(l2, l3);
}

// ---------------------------------------------------------------------------
// MMA helpers
// ---------------------------------------------------------------------------
__device__ __forceinline__ uint32_t smem_u32(const void* p) {
    return (uint32_t)__cvta_generic_to_shared(p);
}
__device__ __forceinline__ void ldm_x4(uint32_t addr, uint32_t* r) {
    asm volatile("ldmatrix.sync.aligned.m8n8.x4.shared.b16 {%0,%1,%2,%3}, [%4];"
                 : "=r"(r[0]), "=r"(r[1]), "=r"(r[2]), "=r"(r[3]) : "r"(addr));
}
__device__ __forceinline__ void ldm_x4_t(uint32_t addr, uint32_t* r) {
    asm volatile("ldmatrix.sync.aligned.m8n8.x4.trans.shared.b16 {%0,%1,%2,%3}, [%4];"
                 : "=r"(r[0]), "=r"(r[1]), "=r"(r[2]), "=r"(r[3]) : "r"(addr));
}
__device__ __forceinline__ void mma_bf16(float* c, const uint32_t* a, uint32_t b0, uint32_t b1) {
    asm volatile("mma.sync.aligned.m16n8k16.row.col.f32.bf16.bf16.f32 "
                 "{%0,%1,%2,%3}, {%4,%5,%6,%7}, {%8,%9}, {%0,%1,%2,%3};"
                 : "+f"(c[0]), "+f"(c[1]), "+f"(c[2]), "+f"(c[3])
                 : "r"(a[0]), "r"(a[1]), "r"(a[2]), "r"(a[3]), "r"(b0), "r"(b1));
}
__device__ __forceinline__ void split2(float v0, float v1, uint32_t& hi, uint32_t& lo) {
    __nv_bfloat162 h = __floats2bfloat162_rn(v0, v1);
    __nv_bfloat162 l = __floats2bfloat162_rn(v0 - __bfloat162float(h.x),
                                             v1 - __bfloat162float(h.y));
    hi = reinterpret_cast<uint32_t&>(h);
    lo = reinterpret_cast<uint32_t&>(l);
}

// ---------------------------------------------------------------------------
// Tensor-core NT GEMM, split-bf16 x3, fp32 accumulate.
// mode 0: fp32 out + bias  (A = attn-out hi/lo)
// mode 1: fused QKV, N=3072, epilogue splits to g_q/g_k/g_v (Q scaled 0.125)
// ---------------------------------------------------------------------------
#define BK 32
#define SST 40

__global__ __launch_bounds__(256, 1)
void gemm_nt_tc(int aSel, int wSel, const float* __restrict__ bias,
                float* __restrict__ Cout, int mode, int M, int N, int K)
{
    const __nv_bfloat16* Ah = aSel ? g_ah : g_xh;
    const __nv_bfloat16* Al = aSel ? g_al : g_xl;
    const __nv_bfloat16* Wh = g_wh[wSel];
    const __nv_bfloat16* Wl = g_wl[wSel];

    __shared__ __nv_bfloat16 sm[4][128 * SST];

    const int tid  = threadIdx.x;
    const int warp = tid >> 5, lane = tid & 31;
    const int wm = warp >> 1, wn = warp & 1;
    const int m0 = blockIdx.y * 128, n0 = blockIdx.x * 128;

    const int lrow = tid >> 1;
    const int lcol = (tid & 1) * 16;
    const size_t gA = (size_t)(m0 + lrow) * K + lcol;
    const size_t gW = (size_t)(n0 + lrow) * K + lcol;
    const int sdst = lrow * SST + lcol;

    float acc[2][8][4];
#pragma unroll
    for (int i = 0; i < 2; ++i)
#pragma unroll
        for (int j = 0; j < 8; ++j)
#pragma unroll
            for (int t = 0; t < 4; ++t) acc[i][j][t] = 0.f;

    for (int k0 = 0; k0 < K; k0 += BK) {
        const int4* pAh = (const int4*)(Ah + gA + k0);
        const int4* pAl = (const int4*)(Al + gA + k0);
        const int4* pWh = (const int4*)(Wh + gW + k0);
        const int4* pWl = (const int4*)(Wl + gW + k0);
        *(int4*)&sm[0][sdst] = pAh[0];  *(int4*)&sm[0][sdst + 8] = pAh[1];
        *(int4*)&sm[1][sdst] = pAl[0];  *(int4*)&sm[1][sdst + 8] = pAl[1];
        *(int4*)&sm[2][sdst] = pWh[0];  *(int4*)&sm[2][sdst + 8] = pWh[1];
        *(int4*)&sm[3][sdst] = pWl[0];  *(int4*)&sm[3][sdst + 8] = pWl[1];
        __syncthreads();

#pragma unroll
        for (int ks = 0; ks < BK; ks += 16) {
            uint32_t aH[2][4], aL[2][4], bH[4][4], bL[4][4];
            const int arow = wm * 32 + (lane & 15);
            const int acol = ks + ((lane >> 4) << 3);
#pragma unroll
            for (int mt = 0; mt < 2; ++mt) {
                ldm_x4(smem_u32(&sm[0][(arow + mt * 16) * SST + acol]), aH[mt]);
                ldm_x4(smem_u32(&sm[1][(arow + mt * 16) * SST + acol]), aL[mt]);
            }
            const int brow = wn * 64 + ((lane >> 4) << 3) + (lane & 7);
            const int bcol = ks + ((lane >> 3) & 1) * 8;
#pragma unroll
            for (int nn = 0; nn < 4; ++nn) {
                ldm_x4(smem_u32(&sm[2][(brow + nn * 16) * SST + bcol]), bH[nn]);
                ldm_x4(smem_u32(&sm[3][(brow + nn * 16) * SST + bcol]), bL[nn]);
            }
#pragma unroll
            for (int mt = 0; mt < 2; ++mt)
#pragma unroll
                for (int nt = 0; nt < 8; ++nt) {
                    const int p = nt >> 1, q = (nt & 1) * 2;
                    mma_bf16(acc[mt][nt], aH[mt], bH[p][q], bH[p][q + 1]);
                    mma_bf16(acc[mt][nt], aH[mt], bL[p][q], bL[p][q + 1]);
                    mma_bf16(acc[mt][nt], aL[mt], bH[p][q], bH[p][q + 1]);
                }
        }
        __syncthreads();
    }

#pragma unroll
    for (int mt = 0; mt < 2; ++mt) {
#pragma unroll
        for (int nt = 0; nt < 8; ++nt) {
            const int m = m0 + wm * 32 + mt * 16 + (lane >> 2);
            const int n = n0 + wn * 64 + nt * 8 + (lane & 3) * 2;
            if (mode == 0) {
                float b0 = bias[n], b1 = bias[n + 1];
                *(float2*)&Cout[(size_t)m * N + n] =
                    make_float2(acc[mt][nt][0] + b0, acc[mt][nt][1] + b1);
                *(float2*)&Cout[(size_t)(m + 8) * N + n] =
                    make_float2(acc[mt][nt][2] + b0, acc[mt][nt][3] + b1);
            } else {
                const int arr = n >> 10;
                const int nc  = n & 1023;
                const float s = (arr == 0) ? 0.125f : 1.f;
                __nv_bfloat16 *H, *L;
                if (arr == 0)      { H = g_qh; L = g_ql; }
                else if (arr == 1) { H = g_kh; L = g_kl; }
                else               { H = g_vh; L = g_vl; }
                uint32_t h01, l01, h23, l23;
                split2(acc[mt][nt][0] * s, acc[mt][nt][1] * s, h01, l01);
                split2(acc[mt][nt][2] * s, acc[mt][nt][3] * s, h23, l23);
                const size_t o0 = (size_t)m * DD + nc;
                const size_t o1 = (size_t)(m + 8) * DD + nc;
                *(uint32_t*)&H[o0] = h01;  *(uint32_t*)&L[o0] = l01;
                *(uint32_t*)&H[o1] = h23;  *(uint32_t*)&L[o1] = l23;
            }
        }
    }
}

// ---------------------------------------------------------------------------
// Tensor-core causal flash attention.
// Block: 128 q rows of one (b,h), 256 threads = 8 warps, 16 q rows per warp.
// S = Q·K^T 3-pass split-bf16; online softmax in accum registers; P·V 3-pass.
// Emits split-bf16 attn-out into g_ah/g_al.
// ---------------------------------------------------------------------------
__global__ __launch_bounds__(256, 1)
void flash_attn_tc()
{
    const int qb = gridDim.x - 1 - blockIdx.x;  // heavy blocks launch first
    const int h  = blockIdx.y;
    const int b  = blockIdx.z;
    const int tid  = threadIdx.x;
    const int warp = tid >> 5, lane = tid & 31;

    __shared__ __align__(16) __nv_bfloat16 sm[256 * 72];

    const int q0 = qb * 128;
    const int qbase = q0 + warp * 16;

    // ---- stage Q (hi rows 0..127, lo rows 128..255), stride 72 ----
    {
        const size_t g0 = ((size_t)(b * TT + q0)) * DD + h * HD;
#pragma unroll
        for (int i = 0; i < 8; ++i) {
            int idx = tid + i * 256;            // 0..2047 int4
            int mat = idx >> 10;                // 0=hi, 1=lo
            int w   = idx & 1023;
            int row = w >> 3;
            int col = (w & 7) * 8;
            const __nv_bfloat16* src = mat ? g_ql : g_qh;
            *(int4*)&sm[(mat * 128 + row) * 72 + col] =
                *(const int4*)&src[g0 + (size_t)row * DD + col];
        }
    }
    __syncthreads();

    uint32_t aQh[4][4], aQl[4][4];
    {
        const int arow = warp * 16 + (lane & 15);
#pragma unroll
        for (int c = 0; c < 4; ++c) {
            const int acol = c * 16 + ((lane >> 4) << 3);
            ldm_x4(smem_u32(&sm[arow * 72 + acol]), aQh[c]);
            ldm_x4(smem_u32(&sm[(128 + arow) * 72 + acol]), aQl[c]);
        }
    }
    __syncthreads();

    float oacc[8][4];
#pragma unroll
    for (int nt = 0; nt < 8; ++nt)
#pragma unroll
        for (int t = 0; t < 4; ++t) oacc[nt][t] = 0.f;
    float m0 = 0.f, m1 = 0.f, l0 = 0.f, l1 = 0.f;

    const int r0i = qbase + (lane >> 2);
    const int r1i = r0i + 8;

    const int nk = q0 + 128;
    for (int kt = 0; kt < nk; kt += 64) {
        // ---- stage K,V tiles: rows 0-63 Kh, 64-127 Kl, 128-191 Vh, 192-255 Vl
        {
            const size_t gk = ((size_t)(b * TT + kt)) * DD + h * HD;
#pragma unroll
            for (int i = 0; i < 8; ++i) {
                int idx = tid + i * 256;        // 0..2047 int4
                int mat = idx >> 9;             // 0..3
                int w   = idx & 511;
                int row = w >> 3;
                int col = (w & 7) * 8;
                const __nv_bfloat16* src = (mat == 0) ? g_kh : (mat == 1) ? g_kl
                                          : (mat == 2) ? g_vh : g_vl;
                *(int4*)&sm[(mat * 64 + row) * 72 + col] =
                    *(const int4*)&src[gk + (size_t)row * DD + col];
            }
        }
        __syncthreads();

        if (kt <= qbase) {
            // ---- S = Q K^T (3-pass split) ----
            float sacc[8][4];
#pragma unroll
            for (int nt = 0; nt < 8; ++nt)
#pragma unroll
                for (int t = 0; t < 4; ++t) sacc[nt][t] = 0.f;

            const int brow = ((lane >> 4) << 3) + (lane & 7);
#pragma unroll
            for (int c = 0; c < 4; ++c) {
                uint32_t bKh[4][4], bKl[4][4];
                const int bcol = c * 16 + ((lane >> 3) & 1) * 8;
#pragma unroll
                for (int p = 0; p < 4; ++p) {
                    ldm_x4(smem_u32(&sm[(p * 16 + brow) * 72 + bcol]), bKh[p]);
                    ldm_x4(smem_u32(&sm[(64 + p * 16 + brow) * 72 + bcol]), bKl[p]);
                }
#pragma unroll
                for (int nt = 0; nt < 8; ++nt) {
                    const int p = nt >> 1, q = (nt & 1) * 2;
                    mma_bf16(sacc[nt], aQh[c], bKh[p][q], bKh[p][q + 1]);
                    mma_bf16(sacc[nt], aQh[c], bKl[p][q], bKl[p][q + 1]);
                    mma_bf16(sacc[nt], aQl[c], bKh[p][q], bKh[p][q + 1]);
                }
            }

            // ---- causal mask (diagonal tiles only) ----
            if (kt + 63 > qbase) {
#pragma unroll
                for (int nt = 0; nt < 8; ++nt) {
                    const int cb = kt + nt * 8 + (lane & 3) * 2;
                    if (cb     > r0i) sacc[nt][0] = -1e30f;
                    if (cb + 1 > r0i) sacc[nt][1] = -1e30f;
                    if (cb     > r1i) sacc[nt][2] = -1e30f;
                    if (cb + 1 > r1i) sacc[nt][3] = -1e30f;
                }
            }

            // ---- online softmax ----
            float tm0 = -1e30f, tm1 = -1e30f;
#pragma unroll
            for (int nt = 0; nt < 8; ++nt) {
                tm0 = fmaxf(tm0, fmaxf(sacc[nt][0], sacc[nt][1]));
                tm1 = fmaxf(tm1, fmaxf(sacc[nt][2], sacc[nt][3]));
            }
            tm0 = fmaxf(tm0, __shfl_xor_sync(0xffffffffu, tm0, 1));
            tm0 = fmaxf(tm0, __shfl_xor_sync(0xffffffffu, tm0, 2));
            tm1 = fmaxf(tm1, __shfl_xor_sync(0xffffffffu, tm1, 1));
            tm1 = fmaxf(tm1, __shfl_xor_sync(0xffffffffu, tm1, 2));

            const float mn0 = fmaxf(m0, tm0), mn1 = fmaxf(m1, tm1);
            const float c0 = __expf(m0 - mn0), c1 = __expf(m1 - mn1);
            m0 = mn0; m1 = mn1;
            l0 *= c0;  l1 *= c1;
#pragma unroll
            for (int nt = 0; nt < 8; ++nt) {
                oacc[nt][0] *= c0; oacc[nt][1] *= c0;
                oacc[nt][2] *= c1; oacc[nt][3] *= c1;
            }

            uint32_t aPh[4][4], aPl[4][4];
            float ls0 = 0.f, ls1 = 0.f;
#pragma unroll
            for (int nt = 0; nt < 8; ++nt) {
                const float p0 = __expf(sacc[nt][0] - mn0);
                const float p1 = __expf(sacc[nt][1] - mn0);
                const float p2 = __expf(sacc[nt][2] - mn1);
                const float p3 = __expf(sacc[nt][3] - mn1);
                ls0 += p0 + p1;  ls1 += p2 + p3;
                const int c = nt >> 1, rr = (nt & 1) * 2;
                split2(p0, p1, aPh[c][rr],     aPl[c][rr]);
                split2(p2, p3, aPh[c][rr + 1], aPl[c][rr + 1]);
            }
            l0 += ls0;  l1 += ls1;

            // ---- O += P V (3-pass split), V via ldmatrix.trans ----
#pragma unroll
            for (int c = 0; c < 4; ++c) {
                uint32_t bVh[8][2], bVl[8][2];
                const int vrow = c * 16 + ((lane >> 3) & 1) * 8 + (lane & 7);
                const int vcol0 = (lane >> 4) << 3;
#pragma unroll
                for (int pr = 0; pr < 4; ++pr) {
                    uint32_t r[4];
                    ldm_x4_t(smem_u32(&sm[(128 + vrow) * 72 + 16 * pr + vcol0]), r);
                    bVh[2 * pr][0] = r[0]; bVh[2 * pr][1] = r[1];
                    bVh[2 * pr + 1][0] = r[2]; bVh[2 * pr + 1][1] = r[3];
                    ldm_x4_t(smem_u32(&sm[(192 + vrow) * 72 + 16 * pr + vcol0]), r);
                    bVl[2 * pr][0] = r[0]; bVl[2 * pr][1] = r[1];
                    bVl[2 * pr + 1][0] = r[2]; bVl[2 * pr + 1][1] = r[3];
                }
#pragma unroll
                for (int nt = 0; nt < 8; ++nt) {
                    mma_bf16(oacc[nt], aPh[c], bVh[nt][0], bVh[nt][1]);
                    mma_bf16(oacc[nt], aPh[c], bVl[nt][0], bVl[nt][1]);
                    mma_bf16(oacc[nt], aPl[c], bVh[nt][0], bVh[nt][1]);
                }
            }
        }
        __syncthreads();
    }

    // ---- finalize: normalize and emit split-bf16 attn-out ----
    l0 += __shfl_xor_sync(0xffffffffu, l0, 1);
    l0 += __shfl_xor_sync(0xffffffffu, l0, 2);
    l1 += __shfl_xor_sync(0xffffffffu, l1, 1);
    l1 += __shfl_xor_sync(0xffffffffu, l1, 2);
    const float inv0 = 1.f / l0, inv1 = 1.f / l1;

#pragma unroll
    for (int nt = 0; nt < 8; ++nt) {
        const int col = h * HD + nt * 8 + (lane & 3) * 2;
        const size_t o0 = ((size_t)(b * TT + r0i)) * DD + col;
        const size_t o1 = ((size_t)(b * TT + r1i)) * DD + col;
        uint32_t hh, ll;
        split2(oacc[nt][0] * inv0, oacc[nt][1] * inv0, hh, ll);
        *(uint32_t*)&g_ah[o0] = hh;  *(uint32_t*)&g_al[o0] = ll;
        split2(oacc[nt][2] * inv1, oacc[nt][3] * inv1, hh, ll);
        *(uint32_t*)&g_ah[o1] = hh;  *(uint32_t*)&g_al[o1] = ll;
    }
}

// ---------------------------------------------------------------------------
// Launch: inputs per metadata order: x, Wk, Wq, Wv, Wp, bp
// ---------------------------------------------------------------------------
extern "C" void kernel_launch(void* const* d_in, const int* in_sizes, int n_in,
                              void* d_out, int out_size)
{
    const float* x  = (const float*)d_in[0];
    const float* Wk = (const float*)d_in[1];
    const float* Wq = (const float*)d_in[2];
    const float* Wv = (const float*)d_in[3];
    const float* Wp = (const float*)d_in[4];
    const float* bp = (const float*)d_in[5];
    float* out = (float*)d_out;

    // split x and weights into bf16 hi/lo  (slot order: Wq, Wk, Wv, Wp)
    {
        int n4 = MM * DD / 4;
        split_fp32_bf16<<<(n4 + 255) / 256, 256>>>(x, 0, n4);
        int w4 = DD * DD / 4;
        split_fp32_bf16<<<(w4 + 255) / 256, 256>>>(Wq, 2, w4);
        split_fp32_bf16<<<(w4 + 255) / 256, 256>>>(Wk, 3, w4);
        split_fp32_bf16<<<(w4 + 255) / 256, 256>>>(Wv, 4, w4);
        split_fp32_bf16<<<(w4 + 255) / 256, 256>>>(Wp, 5, w4);
    }

    // fused QKV projection (N = 3072, weights slots 0..2 are contiguous)
    dim3 qkvGrid(3 * DD / 128, MM / 128);   // 24 x 64
    gemm_nt_tc<<<qkvGrid, 256>>>(0, 0, nullptr, nullptr, 1, MM, 3 * DD, DD);

    // tensor-core causal flash attention -> g_ah/g_al
    dim3 fGrid(TT / 128, HH, BB);           // 16 x 16 x 4
    flash_attn_tc<<<fGrid, 256>>>();

    // output projection with bias -> d_out (fp32)
    dim3 oGrid(DD / 128, MM / 128);         // 8 x 64
    gemm_nt_tc<<<oGrid, 256>>>(1, 3, bp, out, 0, MM, DD, DD);
}

// round 4
// speedup vs baseline: 2.9444x; 1.1771x over previous
#include <cuda_runtime.h>
#include <cuda_bf16.h>
#include <cstdint>

// Problem constants
#define BB 4
#define TT 2048
#define DD 1024
#define HH 16
#define HD 64
#define MM (BB * TT)   // 8192

// split-bf16 tensors (hi/lo pairs)
__device__ __align__(16) __nv_bfloat16 g_xh[(size_t)MM * DD];
__device__ __align__(16) __nv_bfloat16 g_xl[(size_t)MM * DD];
__device__ __align__(16) __nv_bfloat16 g_ah[(size_t)MM * DD];
__device__ __align__(16) __nv_bfloat16 g_al[(size_t)MM * DD];
__device__ __align__(16) __nv_bfloat16 g_qh[(size_t)MM * DD];
__device__ __align__(16) __nv_bfloat16 g_ql[(size_t)MM * DD];
__device__ __align__(16) __nv_bfloat16 g_kh[(size_t)MM * DD];
__device__ __align__(16) __nv_bfloat16 g_kl[(size_t)MM * DD];
__device__ __align__(16) __nv_bfloat16 g_vh[(size_t)MM * DD];
__device__ __align__(16) __nv_bfloat16 g_vl[(size_t)MM * DD];
__device__ __align__(16) __nv_bfloat16 g_wh[4][(size_t)DD * DD];  // Wq,Wk,Wv,Wp
__device__ __align__(16) __nv_bfloat16 g_wl[4][(size_t)DD * DD];

// ---------------------------------------------------------------------------
// fp32 -> (bf16 hi, bf16 lo) splits
// ---------------------------------------------------------------------------
__device__ __forceinline__ void split_store(float4 v, __nv_bfloat16* H,
                                            __nv_bfloat16* L, size_t i4)
{
    __nv_bfloat16 h0 = __float2bfloat16(v.x), h1 = __float2bfloat16(v.y);
    __nv_bfloat16 h2 = __float2bfloat16(v.z), h3 = __float2bfloat16(v.w);
    __nv_bfloat16 l0 = __float2bfloat16(v.x - __bfloat162float(h0));
    __nv_bfloat16 l1 = __float2bfloat16(v.y - __bfloat162float(h1));
    __nv_bfloat16 l2 = __float2bfloat16(v.z - __bfloat162float(h2));
    __nv_bfloat16 l3 = __float2bfloat16(v.w - __bfloat162float(h3));
    *(__nv_bfloat162*)&H[4 * i4]     = __nv_bfloat162(h0, h1);
    *(__nv_bfloat162*)&H[4 * i4 + 2] = __nv_bfloat162(h2, h3);
    *(__nv_bfloat162*)&L[4 * i4]     = __nv_bfloat162(l0, l1);
    *(__nv_bfloat162*)&L[4 * i4 + 2] = __nv_bfloat162(l2, l3);
}

__global__ void split_x(const float* __restrict__ src, int n4)
{
    int i = blockIdx.x * blockDim.x + threadIdx.x;
    if (i >= n4) return;
    split_store(((const float4*)src)[i], g_xh, g_xl, (size_t)i);
}

// all 4 weights in one launch; blockIdx.y selects the weight
__global__ void split_w(const float* __restrict__ w0, const float* __restrict__ w1,
                        const float* __restrict__ w2, const float* __restrict__ w3,
                        int n4)
{
    int i = blockIdx.x * blockDim.x + threadIdx.x;
    if (i >= n4) return;
    int s = blockIdx.y;
    const float* src = (s == 0) ? w0 : (s == 1) ? w1 : (s == 2) ? w2 : w3;
    split_store(((const float4*)src)[i], g_wh[s], g_wl[s], (size_t)i);
}

// ---------------------------------------------------------------------------
// MMA / cp.async helpers
// ---------------------------------------------------------------------------
__device__ __forceinline__ uint32_t smem_u32(const void* p) {
    return (uint32_t)__cvta_generic_to_shared(p);
}
__device__ __forceinline__ void ldm_x4(uint32_t addr, uint32_t* r) {
    asm volatile("ldmatrix.sync.aligned.m8n8.x4.shared.b16 {%0,%1,%2,%3}, [%4];"
                 : "=r"(r[0]), "=r"(r[1]), "=r"(r[2]), "=r"(r[3]) : "r"(addr));
}
__device__ __forceinline__ void ldm_x4_t(uint32_t addr, uint32_t* r) {
    asm volatile("ldmatrix.sync.aligned.m8n8.x4.trans.shared.b16 {%0,%1,%2,%3}, [%4];"
                 : "=r"(r[0]), "=r"(r[1]), "=r"(r[2]), "=r"(r[3]) : "r"(addr));
}
__device__ __forceinline__ void mma_bf16(float* c, const uint32_t* a, uint32_t b0, uint32_t b1) {
    asm volatile("mma.sync.aligned.m16n8k16.row.col.f32.bf16.bf16.f32 "
                 "{%0,%1,%2,%3}, {%4,%5,%6,%7}, {%8,%9}, {%0,%1,%2,%3};"
                 : "+f"(c[0]), "+f"(c[1]), "+f"(c[2]), "+f"(c[3])
                 : "r"(a[0]), "r"(a[1]), "r"(a[2]), "r"(a[3]), "r"(b0), "r"(b1));
}
__device__ __forceinline__ void cp16(uint32_t dst, const void* src) {
    asm volatile("cp.async.cg.shared.global [%0], [%1], 16;" :: "r"(dst), "l"(src));
}
__device__ __forceinline__ void cp_commit() {
    asm volatile("cp.async.commit_group;");
}
template <int N>
__device__ __forceinline__ void cp_wait() {
    asm volatile("cp.async.wait_group %0;" :: "n"(N));
}
__device__ __forceinline__ void split2(float v0, float v1, uint32_t& hi, uint32_t& lo) {
    __nv_bfloat162 h = __floats2bfloat162_rn(v0, v1);
    __nv_bfloat162 l = __floats2bfloat162_rn(v0 - __bfloat162float(h.x),
                                             v1 - __bfloat162float(h.y));
    hi = reinterpret_cast<uint32_t&>(h);
    lo = reinterpret_cast<uint32_t&>(l);
}

// ---------------------------------------------------------------------------
// Tensor-core NT GEMM, split-bf16 x3, fp32 accumulate, 3-stage cp.async pipe.
// mode 0: fp32 out + bias  (A = attn-out hi/lo)
// mode 1: fused QKV, N=3072, epilogue splits to g_q/g_k/g_v (Q scaled 0.125)
// ---------------------------------------------------------------------------
#define BK 32
#define SST 40
#define STAGES 3
#define MAT_ELEMS (128 * SST)
#define STAGE_ELEMS (4 * MAT_ELEMS)
#define GEMM_SMEM (STAGES * STAGE_ELEMS * 2)   // bytes = 122880

__global__ __launch_bounds__(256, 1)
void gemm_nt_tc(int aSel, int wSel, const float* __restrict__ bias,
                float* __restrict__ Cout, int mode, int M, int N, int K)
{
    const __nv_bfloat16* Ah = aSel ? g_ah : g_xh;
    const __nv_bfloat16* Al = aSel ? g_al : g_xl;
    const __nv_bfloat16* Wh = g_wh[wSel];
    const __nv_bfloat16* Wl = g_wl[wSel];

    extern __shared__ __nv_bfloat16 dsm[];

    const int tid  = threadIdx.x;
    const int warp = tid >> 5, lane = tid & 31;
    const int wm = warp >> 1, wn = warp & 1;
    const int m0 = blockIdx.y * 128, n0 = blockIdx.x * 128;

    // load mapping: thread -> (row, 16-col chunk); 2x cp.async(16B) per matrix
    const int lrow = tid >> 1;
    const int lcol = (tid & 1) * 16;
    const size_t gA = (size_t)(m0 + lrow) * K + lcol;
    const size_t gW = (size_t)(n0 + lrow) * K + lcol;
    const int soff = lrow * SST + lcol;

    const int KITERS = K / BK;

#define ISSUE_STAGE(it, st)                                                    \
    do {                                                                       \
        const int _k0 = (it) * BK;                                             \
        __nv_bfloat16* _s = dsm + (st) * STAGE_ELEMS;                          \
        cp16(smem_u32(_s + 0 * MAT_ELEMS + soff),     Ah + gA + _k0);          \
        cp16(smem_u32(_s + 0 * MAT_ELEMS + soff + 8), Ah + gA + _k0 + 8);      \
        cp16(smem_u32(_s + 1 * MAT_ELEMS + soff),     Al + gA + _k0);          \
        cp16(smem_u32(_s + 1 * MAT_ELEMS + soff + 8), Al + gA + _k0 + 8);      \
        cp16(smem_u32(_s + 2 * MAT_ELEMS + soff),     Wh + gW + _k0);          \
        cp16(smem_u32(_s + 2 * MAT_ELEMS + soff + 8), Wh + gW + _k0 + 8);      \
        cp16(smem_u32(_s + 3 * MAT_ELEMS + soff),     Wl + gW + _k0);          \
        cp16(smem_u32(_s + 3 * MAT_ELEMS + soff + 8), Wl + gW + _k0 + 8);      \
    } while (0)

    float acc[2][8][4];
#pragma unroll
    for (int i = 0; i < 2; ++i)
#pragma unroll
        for (int j = 0; j < 8; ++j)
#pragma unroll
            for (int t = 0; t < 4; ++t) acc[i][j][t] = 0.f;

    // prologue: fill STAGES-1 stages
#pragma unroll
    for (int s = 0; s < STAGES - 1; ++s) {
        ISSUE_STAGE(s, s);
        cp_commit();
    }

    for (int it = 0; it < KITERS; ++it) {
        __syncthreads();                       // prev-stage consumers done
        if (it + STAGES - 1 < KITERS)
            ISSUE_STAGE(it + STAGES - 1, (it + STAGES - 1) % STAGES);
        cp_commit();                           // (possibly empty group)
        cp_wait<STAGES - 1>();                 // stage 'it' landed
        __syncthreads();

        const __nv_bfloat16* s0 = dsm + (it % STAGES) * STAGE_ELEMS;
        const __nv_bfloat16* s1 = s0 + MAT_ELEMS;
        const __nv_bfloat16* s2 = s1 + MAT_ELEMS;
        const __nv_bfloat16* s3 = s2 + MAT_ELEMS;

#pragma unroll
        for (int ks = 0; ks < BK; ks += 16) {
            uint32_t aH[2][4], aL[2][4], bH[4][4], bL[4][4];
            const int arow = wm * 32 + (lane & 15);
            const int acol = ks + ((lane >> 4) << 3);
#pragma unroll
            for (int mt = 0; mt < 2; ++mt) {
                ldm_x4(smem_u32(&s0[(arow + mt * 16) * SST + acol]), aH[mt]);
                ldm_x4(smem_u32(&s1[(arow + mt * 16) * SST + acol]), aL[mt]);
            }
            const int brow = wn * 64 + ((lane >> 4) << 3) + (lane & 7);
            const int bcol = ks + ((lane >> 3) & 1) * 8;
#pragma unroll
            for (int nn = 0; nn < 4; ++nn) {
                ldm_x4(smem_u32(&s2[(brow + nn * 16) * SST + bcol]), bH[nn]);
                ldm_x4(smem_u32(&s3[(brow + nn * 16) * SST + bcol]), bL[nn]);
            }
#pragma unroll
            for (int mt = 0; mt < 2; ++mt)
#pragma unroll
                for (int nt = 0; nt < 8; ++nt) {
                    const int p = nt >> 1, q = (nt & 1) * 2;
                    mma_bf16(acc[mt][nt], aH[mt], bH[p][q], bH[p][q + 1]);
                    mma_bf16(acc[mt][nt], aH[mt], bL[p][q], bL[p][q + 1]);
                    mma_bf16(acc[mt][nt], aL[mt], bH[p][q], bH[p][q + 1]);
                }
        }
    }
#undef ISSUE_STAGE

#pragma unroll
    for (int mt = 0; mt < 2; ++mt) {
#pragma unroll
        for (int nt = 0; nt < 8; ++nt) {
            const int m = m0 + wm * 32 + mt * 16 + (lane >> 2);
            const int n = n0 + wn * 64 + nt * 8 + (lane & 3) * 2;
            if (mode == 0) {
                float b0 = bias[n], b1 = bias[n + 1];
                *(float2*)&Cout[(size_t)m * N + n] =
                    make_float2(acc[mt][nt][0] + b0, acc[mt][nt][1] + b1);
                *(float2*)&Cout[(size_t)(m + 8) * N + n] =
                    make_float2(acc[mt][nt][2] + b0, acc[mt][nt][3] + b1);
            } else {
                const int arr = n >> 10;
                const int nc  = n & 1023;
                const float s = (arr == 0) ? 0.125f : 1.f;
                __nv_bfloat16 *H, *L;
                if (arr == 0)      { H = g_qh; L = g_ql; }
                else if (arr == 1) { H = g_kh; L = g_kl; }
                else               { H = g_vh; L = g_vl; }
                uint32_t h01, l01, h23, l23;
                split2(acc[mt][nt][0] * s, acc[mt][nt][1] * s, h01, l01);
                split2(acc[mt][nt][2] * s, acc[mt][nt][3] * s, h23, l23);
                const size_t o0 = (size_t)m * DD + nc;
                const size_t o1 = (size_t)(m + 8) * DD + nc;
                *(uint32_t*)&H[o0] = h01;  *(uint32_t*)&L[o0] = l01;
                *(uint32_t*)&H[o1] = h23;  *(uint32_t*)&L[o1] = l23;
            }
        }
    }
}

// ---------------------------------------------------------------------------
// Tensor-core causal flash attention (unchanged from R2).
// ---------------------------------------------------------------------------
__global__ __launch_bounds__(256, 1)
void flash_attn_tc()
{
    const int qb = gridDim.x - 1 - blockIdx.x;
    const int h  = blockIdx.y;
    const int b  = blockIdx.z;
    const int tid  = threadIdx.x;
    const int warp = tid >> 5, lane = tid & 31;

    __shared__ __align__(16) __nv_bfloat16 sm[256 * 72];

    const int q0 = qb * 128;
    const int qbase = q0 + warp * 16;

    {
        const size_t g0 = ((size_t)(b * TT + q0)) * DD + h * HD;
#pragma unroll
        for (int i = 0; i < 8; ++i) {
            int idx = tid + i * 256;
            int mat = idx >> 10;
            int w   = idx & 1023;
            int row = w >> 3;
            int col = (w & 7) * 8;
            const __nv_bfloat16* src = mat ? g_ql : g_qh;
            *(int4*)&sm[(mat * 128 + row) * 72 + col] =
                *(const int4*)&src[g0 + (size_t)row * DD + col];
        }
    }
    __syncthreads();

    uint32_t aQh[4][4], aQl[4][4];
    {
        const int arow = warp * 16 + (lane & 15);
#pragma unroll
        for (int c = 0; c < 4; ++c) {
            const int acol = c * 16 + ((lane >> 4) << 3);
            ldm_x4(smem_u32(&sm[arow * 72 + acol]), aQh[c]);
            ldm_x4(smem_u32(&sm[(128 + arow) * 72 + acol]), aQl[c]);
        }
    }
    __syncthreads();

    float oacc[8][4];
#pragma unroll
    for (int nt = 0; nt < 8; ++nt)
#pragma unroll
        for (int t = 0; t < 4; ++t) oacc[nt][t] = 0.f;
    float m0 = 0.f, m1 = 0.f, l0 = 0.f, l1 = 0.f;

    const int r0i = qbase + (lane >> 2);
    const int r1i = r0i + 8;

    const int nk = q0 + 128;
    for (int kt = 0; kt < nk; kt += 64) {
        {
            const size_t gk = ((size_t)(b * TT + kt)) * DD + h * HD;
#pragma unroll
            for (int i = 0; i < 8; ++i) {
                int idx = tid + i * 256;
                int mat = idx >> 9;
                int w   = idx & 511;
                int row = w >> 3;
                int col = (w & 7) * 8;
                const __nv_bfloat16* src = (mat == 0) ? g_kh : (mat == 1) ? g_kl
                                          : (mat == 2) ? g_vh : g_vl;
                *(int4*)&sm[(mat * 64 + row) * 72 + col] =
                    *(const int4*)&src[gk + (size_t)row * DD + col];
            }
        }
        __syncthreads();

        if (kt <= qbase) {
            float sacc[8][4];
#pragma unroll
            for (int nt = 0; nt < 8; ++nt)
#pragma unroll
                for (int t = 0; t < 4; ++t) sacc[nt][t] = 0.f;

            const int brow = ((lane >> 4) << 3) + (lane & 7);
#pragma unroll
            for (int c = 0; c < 4; ++c) {
                uint32_t bKh[4][4], bKl[4][4];
                const int bcol = c * 16 + ((lane >> 3) & 1) * 8;
#pragma unroll
                for (int p = 0; p < 4; ++p) {
                    ldm_x4(smem_u32(&sm[(p * 16 + brow) * 72 + bcol]), bKh[p]);
                    ldm_x4(smem_u32(&sm[(64 + p * 16 + brow) * 72 + bcol]), bKl[p]);
                }
#pragma unroll
                for (int nt = 0; nt < 8; ++nt) {
                    const int p = nt >> 1, q = (nt & 1) * 2;
                    mma_bf16(sacc[nt], aQh[c], bKh[p][q], bKh[p][q + 1]);
                    mma_bf16(sacc[nt], aQh[c], bKl[p][q], bKl[p][q + 1]);
                    mma_bf16(sacc[nt], aQl[c], bKh[p][q], bKh[p][q + 1]);
                }
            }

            if (kt + 63 > qbase) {
#pragma unroll
                for (int nt = 0; nt < 8; ++nt) {
                    const int cb = kt + nt * 8 + (lane & 3) * 2;
                    if (cb     > r0i) sacc[nt][0] = -1e30f;
                    if (cb + 1 > r0i) sacc[nt][1] = -1e30f;
                    if (cb     > r1i) sacc[nt][2] = -1e30f;
                    if (cb + 1 > r1i) sacc[nt][3] = -1e30f;
                }
            }

            float tm0 = -1e30f, tm1 = -1e30f;
#pragma unroll
            for (int nt = 0; nt < 8; ++nt) {
                tm0 = fmaxf(tm0, fmaxf(sacc[nt][0], sacc[nt][1]));
                tm1 = fmaxf(tm1, fmaxf(sacc[nt][2], sacc[nt][3]));
            }
            tm0 = fmaxf(tm0, __shfl_xor_sync(0xffffffffu, tm0, 1));
            tm0 = fmaxf(tm0, __shfl_xor_sync(0xffffffffu, tm0, 2));
            tm1 = fmaxf(tm1, __shfl_xor_sync(0xffffffffu, tm1, 1));
            tm1 = fmaxf(tm1, __shfl_xor_sync(0xffffffffu, tm1, 2));

            const float mn0 = fmaxf(m0, tm0), mn1 = fmaxf(m1, tm1);
            const float c0 = __expf(m0 - mn0), c1 = __expf(m1 - mn1);
            m0 = mn0; m1 = mn1;
            l0 *= c0;  l1 *= c1;
#pragma unroll
            for (int nt = 0; nt < 8; ++nt) {
                oacc[nt][0] *= c0; oacc[nt][1] *= c0;
                oacc[nt][2] *= c1; oacc[nt][3] *= c1;
            }

            uint32_t aPh[4][4], aPl[4][4];
            float ls0 = 0.f, ls1 = 0.f;
#pragma unroll
            for (int nt = 0; nt < 8; ++nt) {
                const float p0 = __expf(sacc[nt][0] - mn0);
                const float p1 = __expf(sacc[nt][1] - mn0);
                const float p2 = __expf(sacc[nt][2] - mn1);
                const float p3 = __expf(sacc[nt][3] - mn1);
                ls0 += p0 + p1;  ls1 += p2 + p3;
                const int c = nt >> 1, rr = (nt & 1) * 2;
                split2(p0, p1, aPh[c][rr],     aPl[c][rr]);
                split2(p2, p3, aPh[c][rr + 1], aPl[c][rr + 1]);
            }
            l0 += ls0;  l1 += ls1;

#pragma unroll
            for (int c = 0; c < 4; ++c) {
                uint32_t bVh[8][2], bVl[8][2];
                const int vrow = c * 16 + ((lane >> 3) & 1) * 8 + (lane & 7);
                const int vcol0 = (lane >> 4) << 3;
#pragma unroll
                for (int pr = 0; pr < 4; ++pr) {
                    uint32_t r[4];
                    ldm_x4_t(smem_u32(&sm[(128 + vrow) * 72 + 16 * pr + vcol0]), r);
                    bVh[2 * pr][0] = r[0]; bVh[2 * pr][1] = r[1];
                    bVh[2 * pr + 1][0] = r[2]; bVh[2 * pr + 1][1] = r[3];
                    ldm_x4_t(smem_u32(&sm[(192 + vrow) * 72 + 16 * pr + vcol0]), r);
                    bVl[2 * pr][0] = r[0]; bVl[2 * pr][1] = r[1];
                    bVl[2 * pr + 1][0] = r[2]; bVl[2 * pr + 1][1] = r[3];
                }
#pragma unroll
                for (int nt = 0; nt < 8; ++nt) {
                    mma_bf16(oacc[nt], aPh[c], bVh[nt][0], bVh[nt][1]);
                    mma_bf16(oacc[nt], aPh[c], bVl[nt][0], bVl[nt][1]);
                    mma_bf16(oacc[nt], aPl[c], bVh[nt][0], bVh[nt][1]);
                }
            }
        }
        __syncthreads();
    }

    l0 += __shfl_xor_sync(0xffffffffu, l0, 1);
    l0 += __shfl_xor_sync(0xffffffffu, l0, 2);
    l1 += __shfl_xor_sync(0xffffffffu, l1, 1);
    l1 += __shfl_xor_sync(0xffffffffu, l1, 2);
    const float inv0 = 1.f / l0, inv1 = 1.f / l1;

#pragma unroll
    for (int nt = 0; nt < 8; ++nt) {
        const int col = h * HD + nt * 8 + (lane & 3) * 2;
        const size_t o0 = ((size_t)(b * TT + r0i)) * DD + col;
        const size_t o1 = ((size_t)(b * TT + r1i)) * DD + col;
        uint32_t hh, ll;
        split2(oacc[nt][0] * inv0, oacc[nt][1] * inv0, hh, ll);
        *(uint32_t*)&g_ah[o0] = hh;  *(uint32_t*)&g_al[o0] = ll;
        split2(oacc[nt][2] * inv1, oacc[nt][3] * inv1, hh, ll);
        *(uint32_t*)&g_ah[o1] = hh;  *(uint32_t*)&g_al[o1] = ll;
    }
}

// ---------------------------------------------------------------------------
// Launch: inputs per metadata order: x, Wk, Wq, Wv, Wp, bp
// ---------------------------------------------------------------------------
extern "C" void kernel_launch(void* const* d_in, const int* in_sizes, int n_in,
                              void* d_out, int out_size)
{
    const float* x  = (const float*)d_in[0];
    const float* Wk = (const float*)d_in[1];
    const float* Wq = (const float*)d_in[2];
    const float* Wv = (const float*)d_in[3];
    const float* Wp = (const float*)d_in[4];
    const float* bp = (const float*)d_in[5];
    float* out = (float*)d_out;

    // opt-in to >48KB dynamic smem (idempotent, not a stream op)
    cudaFuncSetAttribute(gemm_nt_tc, cudaFuncAttributeMaxDynamicSharedMemorySize,
                         GEMM_SMEM);

    // splits: x, then all 4 weights in one launch (slot order: Wq, Wk, Wv, Wp)
    {
        int n4 = MM * DD / 4;
        split_x<<<(n4 + 255) / 256, 256>>>(x, n4);
        int w4 = DD * DD / 4;
        dim3 wg((w4 + 255) / 256, 4);
        split_w<<<wg, 256>>>(Wq, Wk, Wv, Wp, w4);
    }

    // fused QKV projection (N = 3072, weight slots 0..2 contiguous)
    dim3 qkvGrid(3 * DD / 128, MM / 128);   // 24 x 64
    gemm_nt_tc<<<qkvGrid, 256, GEMM_SMEM>>>(0, 0, nullptr, nullptr, 1, MM, 3 * DD, DD);

    // tensor-core causal flash attention -> g_ah/g_al
    dim3 fGrid(TT / 128, HH, BB);           // 16 x 16 x 4
    flash_attn_tc<<<fGrid, 256>>>();

    // output projection with bias -> d_out (fp32)
    dim3 oGrid(DD / 128, MM / 128);         // 8 x 64
    gemm_nt_tc<<<oGrid, 256, GEMM_SMEM>>>(1, 3, bp, out, 0, MM, DD, DD);
}

// round 6
// speedup vs baseline: 6.1347x; 2.0836x over previous
#include <cuda_runtime.h>
#include <cuda_fp16.h>
#include <cstdint>

// Problem constants
#define BB 4
#define TT 2048
#define DD 1024
#define HH 16
#define HD 64
#define MM (BB * TT)   // 8192

// fp16 tensors
__device__ __align__(16) __half g_x16[(size_t)MM * DD];
__device__ __align__(16) __half g_a16[(size_t)MM * DD];
__device__ __align__(16) __half g_q16[(size_t)MM * DD];
__device__ __align__(16) __half g_k16[(size_t)MM * DD];
__device__ __align__(16) __half g_v16[(size_t)MM * DD];
__device__ __align__(16) __half g_w16[4][(size_t)DD * DD];   // Wq,Wk,Wv,Wp

// ---------------------------------------------------------------------------
// fp32 -> fp16 converts
// ---------------------------------------------------------------------------
__global__ void cvt_x(const float* __restrict__ src, int n4)
{
    int i = blockIdx.x * blockDim.x + threadIdx.x;
    if (i >= n4) return;
    float4 v = ((const float4*)src)[i];
    *(__half2*)&g_x16[4 * (size_t)i]     = __floats2half2_rn(v.x, v.y);
    *(__half2*)&g_x16[4 * (size_t)i + 2] = __floats2half2_rn(v.z, v.w);
}

__global__ void cvt_w(const float* __restrict__ w0, const float* __restrict__ w1,
                      const float* __restrict__ w2, const float* __restrict__ w3,
                      int n4)
{
    int i = blockIdx.x * blockDim.x + threadIdx.x;
    if (i >= n4) return;
    int s = blockIdx.y;
    const float* src = (s == 0) ? w0 : (s == 1) ? w1 : (s == 2) ? w2 : w3;
    float4 v = ((const float4*)src)[i];
    __half* H = g_w16[s];
    *(__half2*)&H[4 * (size_t)i]     = __floats2half2_rn(v.x, v.y);
    *(__half2*)&H[4 * (size_t)i + 2] = __floats2half2_rn(v.z, v.w);
}

// ---------------------------------------------------------------------------
// MMA / cp.async helpers
// ---------------------------------------------------------------------------
__device__ __forceinline__ uint32_t smem_u32(const void* p) {
    return (uint32_t)__cvta_generic_to_shared(p);
}
__device__ __forceinline__ void ldm_x4(uint32_t addr, uint32_t* r) {
    asm volatile("ldmatrix.sync.aligned.m8n8.x4.shared.b16 {%0,%1,%2,%3}, [%4];"
                 : "=r"(r[0]), "=r"(r[1]), "=r"(r[2]), "=r"(r[3]) : "r"(addr));
}
__device__ __forceinline__ void ldm_x4_t(uint32_t addr, uint32_t* r) {
    asm volatile("ldmatrix.sync.aligned.m8n8.x4.trans.shared.b16 {%0,%1,%2,%3}, [%4];"
                 : "=r"(r[0]), "=r"(r[1]), "=r"(r[2]), "=r"(r[3]) : "r"(addr));
}
__device__ __forceinline__ void mma_f16(float* c, const uint32_t* a, uint32_t b0, uint32_t b1) {
    asm volatile("mma.sync.aligned.m16n8k16.row.col.f32.f16.f16.f32 "
                 "{%0,%1,%2,%3}, {%4,%5,%6,%7}, {%8,%9}, {%0,%1,%2,%3};"
                 : "+f"(c[0]), "+f"(c[1]), "+f"(c[2]), "+f"(c[3])
                 : "r"(a[0]), "r"(a[1]), "r"(a[2]), "r"(a[3]), "r"(b0), "r"(b1));
}
__device__ __forceinline__ void cp16(uint32_t dst, const void* src) {
    asm volatile("cp.async.cg.shared.global [%0], [%1], 16;" :: "r"(dst), "l"(src));
}
__device__ __forceinline__ void cp_commit() {
    asm volatile("cp.async.commit_group;");
}
template <int N>
__device__ __forceinline__ void cp_wait() {
    asm volatile("cp.async.wait_group %0;" :: "n"(N));
}

// ---------------------------------------------------------------------------
// fp16 NT GEMM (single pass), fp32 accumulate, 3-stage cp.async pipeline.
// C[m,n] = sum_k A[m,k]*W[n,k].  Block 128x128, BK=32, 256 threads.
// mode 0: fp32 out + bias.  mode 1: fused QKV epilogue (fp16 store, Q*0.125)
// ---------------------------------------------------------------------------
#define BK 32
#define SST 40
#define STAGES 3
#define MAT_ELEMS (128 * SST)
#define STAGE_ELEMS (2 * MAT_ELEMS)
#define GEMM_SMEM (STAGES * STAGE_ELEMS * 2)   // 61440 bytes

__global__ __launch_bounds__(256, 1)
void gemm_nt_f16(int aSel, int wSel, const float* __restrict__ bias,
                 float* __restrict__ Cout, int mode, int M, int N, int K)
{
    const __half* A = aSel ? g_a16 : g_x16;
    const __half* W = g_w16[wSel];

    extern __shared__ __half dsm[];

    const int tid  = threadIdx.x;
    const int warp = tid >> 5, lane = tid & 31;
    const int wm = warp >> 1, wn = warp & 1;
    const int m0 = blockIdx.y * 128, n0 = blockIdx.x * 128;

    const int lrow = tid >> 1;
    const int lcol = (tid & 1) * 16;
    const size_t gA = (size_t)(m0 + lrow) * K + lcol;
    const size_t gW = (size_t)(n0 + lrow) * K + lcol;
    const int soff = lrow * SST + lcol;

    const int KITERS = K / BK;

#define ISSUE_STAGE(it, st)                                                    \
    do {                                                                       \
        const int _k0 = (it) * BK;                                             \
        __half* _s = dsm + (st) * STAGE_ELEMS;                                 \
        cp16(smem_u32(_s + soff),                 A + gA + _k0);               \
        cp16(smem_u32(_s + soff + 8),             A + gA + _k0 + 8);           \
        cp16(smem_u32(_s + MAT_ELEMS + soff),     W + gW + _k0);               \
        cp16(smem_u32(_s + MAT_ELEMS + soff + 8), W + gW + _k0 + 8);           \
    } while (0)

    float acc[2][8][4];
#pragma unroll
    for (int i = 0; i < 2; ++i)
#pragma unroll
        for (int j = 0; j < 8; ++j)
#pragma unroll
            for (int t = 0; t < 4; ++t) acc[i][j][t] = 0.f;

#pragma unroll
    for (int s = 0; s < STAGES - 1; ++s) {
        ISSUE_STAGE(s, s);
        cp_commit();
    }

    for (int it = 0; it < KITERS; ++it) {
        __syncthreads();
        if (it + STAGES - 1 < KITERS)
            ISSUE_STAGE(it + STAGES - 1, (it + STAGES - 1) % STAGES);
        cp_commit();
        cp_wait<STAGES - 1>();
        __syncthreads();

        const __half* sA = dsm + (it % STAGES) * STAGE_ELEMS;
        const __half* sW = sA + MAT_ELEMS;

#pragma unroll
        for (int ks = 0; ks < BK; ks += 16) {
            uint32_t aF[2][4], bF[4][4];
            const int arow = wm * 32 + (lane & 15);
            const int acol = ks + ((lane >> 4) << 3);
#pragma unroll
            for (int mt = 0; mt < 2; ++mt)
                ldm_x4(smem_u32(&sA[(arow + mt * 16) * SST + acol]), aF[mt]);
            const int brow = wn * 64 + ((lane >> 4) << 3) + (lane & 7);
            const int bcol = ks + ((lane >> 3) & 1) * 8;
#pragma unroll
            for (int nn = 0; nn < 4; ++nn)
                ldm_x4(smem_u32(&sW[(brow + nn * 16) * SST + bcol]), bF[nn]);
#pragma unroll
            for (int mt = 0; mt < 2; ++mt)
#pragma unroll
                for (int nt = 0; nt < 8; ++nt) {
                    const int p = nt >> 1, q = (nt & 1) * 2;
                    mma_f16(acc[mt][nt], aF[mt], bF[p][q], bF[p][q + 1]);
                }
        }
    }
#undef ISSUE_STAGE

#pragma unroll
    for (int mt = 0; mt < 2; ++mt) {
#pragma unroll
        for (int nt = 0; nt < 8; ++nt) {
            const int m = m0 + wm * 32 + mt * 16 + (lane >> 2);
            const int n = n0 + wn * 64 + nt * 8 + (lane & 3) * 2;
            if (mode == 0) {
                float b0 = bias[n], b1 = bias[n + 1];
                *(float2*)&Cout[(size_t)m * N + n] =
                    make_float2(acc[mt][nt][0] + b0, acc[mt][nt][1] + b1);
                *(float2*)&Cout[(size_t)(m + 8) * N + n] =
                    make_float2(acc[mt][nt][2] + b0, acc[mt][nt][3] + b1);
            } else {
                const int arr = n >> 10;
                const int nc  = n & 1023;
                const float s = (arr == 0) ? 0.125f : 1.f;
                __half* H = (arr == 0) ? g_q16 : (arr == 1) ? g_k16 : g_v16;
                __half2 v0 = __floats2half2_rn(acc[mt][nt][0] * s, acc[mt][nt][1] * s);
                __half2 v1 = __floats2half2_rn(acc[mt][nt][2] * s, acc[mt][nt][3] * s);
                *(__half2*)&H[(size_t)m * DD + nc]       = v0;
                *(__half2*)&H[(size_t)(m + 8) * DD + nc] = v1;
            }
        }
    }
}

// ---------------------------------------------------------------------------
// fp16 tensor-core causal flash attention.
// Block: 128 q rows of one (b,h), 256 threads = 8 warps, 16 q rows/warp.
// ---------------------------------------------------------------------------
__global__ __launch_bounds__(256, 2)
void flash_attn_f16()
{
    const int qb = gridDim.x - 1 - blockIdx.x;   // heavy blocks first
    const int h  = blockIdx.y;
    const int b  = blockIdx.z;
    const int tid  = threadIdx.x;
    const int warp = tid >> 5, lane = tid & 31;

    __shared__ __align__(16) __half sm[128 * 72];

    const int q0 = qb * 128;
    const int qbase = q0 + warp * 16;

    // stage Q tile [128 x 64], stride 72
    {
        const size_t g0 = ((size_t)(b * TT + q0)) * DD + h * HD;
#pragma unroll
        for (int i = 0; i < 4; ++i) {
            int idx = tid + i * 256;           // 0..1023 int4
            int row = idx >> 3;
            int col = (idx & 7) * 8;
            *(int4*)&sm[row * 72 + col] =
                *(const int4*)&g_q16[g0 + (size_t)row * DD + col];
        }
    }
    __syncthreads();

    uint32_t aQ[4][4];
    {
        const int arow = warp * 16 + (lane & 15);
#pragma unroll
        for (int c = 0; c < 4; ++c) {
            const int acol = c * 16 + ((lane >> 4) << 3);
            ldm_x4(smem_u32(&sm[arow * 72 + acol]), aQ[c]);
        }
    }
    __syncthreads();

    float oacc[8][4];
#pragma unroll
    for (int nt = 0; nt < 8; ++nt)
#pragma unroll
        for (int t = 0; t < 4; ++t) oacc[nt][t] = 0.f;
    float m0 = 0.f, m1 = 0.f, l0 = 0.f, l1 = 0.f;

    const int r0i = qbase + (lane >> 2);
    const int r1i = r0i + 8;

    const int nk = q0 + 128;
    for (int kt = 0; kt < nk; kt += 64) {
        // stage K [0..63] and V [64..127]
        {
            const size_t gk = ((size_t)(b * TT + kt)) * DD + h * HD;
#pragma unroll
            for (int i = 0; i < 4; ++i) {
                int idx = tid + i * 256;       // 0..1023 int4
                int mat = idx >> 9;            // 0=K, 1=V
                int w   = idx & 511;
                int row = w >> 3;
                int col = (w & 7) * 8;
                const __half* src = mat ? g_v16 : g_k16;
                *(int4*)&sm[(mat * 64 + row) * 72 + col] =
                    *(const int4*)&src[gk + (size_t)row * DD + col];
            }
        }
        __syncthreads();

        if (kt <= qbase) {
            // S = Q K^T
            float sacc[8][4];
#pragma unroll
            for (int nt = 0; nt < 8; ++nt)
#pragma unroll
                for (int t = 0; t < 4; ++t) sacc[nt][t] = 0.f;

            const int brow = ((lane >> 4) << 3) + (lane & 7);
#pragma unroll
            for (int c = 0; c < 4; ++c) {
                uint32_t bK[4][4];
                const int bcol = c * 16 + ((lane >> 3) & 1) * 8;
#pragma unroll
                for (int p = 0; p < 4; ++p)
                    ldm_x4(smem_u32(&sm[(p * 16 + brow) * 72 + bcol]), bK[p]);
#pragma unroll
                for (int nt = 0; nt < 8; ++nt) {
                    const int p = nt >> 1, q = (nt & 1) * 2;
                    mma_f16(sacc[nt], aQ[c], bK[p][q], bK[p][q + 1]);
                }
            }

            // causal mask on diagonal tiles
            if (kt + 63 > qbase) {
#pragma unroll
                for (int nt = 0; nt < 8; ++nt) {
                    const int cb = kt + nt * 8 + (lane & 3) * 2;
                    if (cb     > r0i) sacc[nt][0] = -1e30f;
                    if (cb + 1 > r0i) sacc[nt][1] = -1e30f;
                    if (cb     > r1i) sacc[nt][2] = -1e30f;
                    if (cb + 1 > r1i) sacc[nt][3] = -1e30f;
                }
            }

            // online softmax
            float tm0 = -1e30f, tm1 = -1e30f;
#pragma unroll
            for (int nt = 0; nt < 8; ++nt) {
                tm0 = fmaxf(tm0, fmaxf(sacc[nt][0], sacc[nt][1]));
                tm1 = fmaxf(tm1, fmaxf(sacc[nt][2], sacc[nt][3]));
            }
            tm0 = fmaxf(tm0, __shfl_xor_sync(0xffffffffu, tm0, 1));
            tm0 = fmaxf(tm0, __shfl_xor_sync(0xffffffffu, tm0, 2));
            tm1 = fmaxf(tm1, __shfl_xor_sync(0xffffffffu, tm1, 1));
            tm1 = fmaxf(tm1, __shfl_xor_sync(0xffffffffu, tm1, 2));

            const float mn0 = fmaxf(m0, tm0), mn1 = fmaxf(m1, tm1);
            const float c0 = __expf(m0 - mn0), c1 = __expf(m1 - mn1);
            m0 = mn0; m1 = mn1;
            l0 *= c0;  l1 *= c1;
#pragma unroll
            for (int nt = 0; nt < 8; ++nt) {
                oacc[nt][0] *= c0; oacc[nt][1] *= c0;
                oacc[nt][2] *= c1; oacc[nt][3] *= c1;
            }

            uint32_t aP[4][4];
            float ls0 = 0.f, ls1 = 0.f;
#pragma unroll
            for (int nt = 0; nt < 8; ++nt) {
                const float p0 = __expf(sacc[nt][0] - mn0);
                const float p1 = __expf(sacc[nt][1] - mn0);
                const float p2 = __expf(sacc[nt][2] - mn1);
                const float p3 = __expf(sacc[nt][3] - mn1);
                ls0 += p0 + p1;  ls1 += p2 + p3;
                const int c = nt >> 1, rr = (nt & 1) * 2;
                __half2 h01 = __floats2half2_rn(p0, p1);
                __half2 h23 = __floats2half2_rn(p2, p3);
                aP[c][rr]     = reinterpret_cast<uint32_t&>(h01);
                aP[c][rr + 1] = reinterpret_cast<uint32_t&>(h23);
            }
            l0 += ls0;  l1 += ls1;

            // O += P V, V via ldmatrix.trans (V at smem rows 64..127)
#pragma unroll
            for (int c = 0; c < 4; ++c) {
                uint32_t bV[8][2];
                const int vrow = c * 16 + ((lane >> 3) & 1) * 8 + (lane & 7);
                const int vcol0 = (lane >> 4) << 3;
#pragma unroll
                for (int pr = 0; pr < 4; ++pr) {
                    uint32_t r[4];
                    ldm_x4_t(smem_u32(&sm[(64 + vrow) * 72 + 16 * pr + vcol0]), r);
                    bV[2 * pr][0] = r[0]; bV[2 * pr][1] = r[1];
                    bV[2 * pr + 1][0] = r[2]; bV[2 * pr + 1][1] = r[3];
                }
#pragma unroll
                for (int nt = 0; nt < 8; ++nt)
                    mma_f16(oacc[nt], aP[c], bV[nt][0], bV[nt][1]);
            }
        }
        __syncthreads();
    }

    // finalize: normalize, emit fp16 attn-out
    l0 += __shfl_xor_sync(0xffffffffu, l0, 1);
    l0 += __shfl_xor_sync(0xffffffffu, l0, 2);
    l1 += __shfl_xor_sync(0xffffffffu, l1, 1);
    l1 += __shfl_xor_sync(0xffffffffu, l1, 2);
    const float inv0 = 1.f / l0, inv1 = 1.f / l1;

#pragma unroll
    for (int nt = 0; nt < 8; ++nt) {
        const int col = h * HD + nt * 8 + (lane & 3) * 2;
        const size_t o0 = ((size_t)(b * TT + r0i)) * DD + col;
        const size_t o1 = ((size_t)(b * TT + r1i)) * DD + col;
        *(__half2*)&g_a16[o0] = __floats2half2_rn(oacc[nt][0] * inv0, oacc[nt][1] * inv0);
        *(__half2*)&g_a16[o1] = __floats2half2_rn(oacc[nt][2] * inv1, oacc[nt][3] * inv1);
    }
}

// ---------------------------------------------------------------------------
// Launch: inputs per metadata order: x, Wk, Wq, Wv, Wp, bp
// ---------------------------------------------------------------------------
extern "C" void kernel_launch(void* const* d_in, const int* in_sizes, int n_in,
                              void* d_out, int out_size)
{
    const float* x  = (const float*)d_in[0];
    const float* Wk = (const float*)d_in[1];
    const float* Wq = (const float*)d_in[2];
    const float* Wv = (const float*)d_in[3];
    const float* Wp = (const float*)d_in[4];
    const float* bp = (const float*)d_in[5];
    float* out = (float*)d_out;

    cudaFuncSetAttribute(gemm_nt_f16, cudaFuncAttributeMaxDynamicSharedMemorySize,
                         GEMM_SMEM);

    // converts: x, then all 4 weights (slot order: Wq, Wk, Wv, Wp)
    {
        int n4 = MM * DD / 4;
        cvt_x<<<(n4 + 255) / 256, 256>>>(x, n4);
        int w4 = DD * DD / 4;
        dim3 wg((w4 + 255) / 256, 4);
        cvt_w<<<wg, 256>>>(Wq, Wk, Wv, Wp, w4);
    }

    // fused QKV projection: N = 3072 (weight slots 0..2 contiguous)
    dim3 qkvGrid(3 * DD / 128, MM / 128);   // 24 x 64
    gemm_nt_f16<<<qkvGrid, 256, GEMM_SMEM>>>(0, 0, nullptr, nullptr, 1, MM, 3 * DD, DD);

    // fp16 causal flash attention -> g_a16
    dim3 fGrid(TT / 128, HH, BB);           // 16 x 16 x 4
    flash_attn_f16<<<fGrid, 256>>>();

    // output projection with bias -> d_out (fp32)
    dim3 oGrid(DD / 128, MM / 128);         // 8 x 64
    gemm_nt_f16<<<oGrid, 256, GEMM_SMEM>>>(1, 3, bp, out, 0, MM, DD, DD);
}

// round 7
// speedup vs baseline: 7.7110x; 1.2569x over previous
#include <cuda_runtime.h>
#include <cuda_fp16.h>
#include <cstdint>

// Problem constants
#define BB 4
#define TT 2048
#define DD 1024
#define HH 16
#define HD 64
#define MM (BB * TT)   // 8192

#define LOG2E 1.44269504088896340736f

// fp16 tensors
__device__ __align__(16) __half g_x16[(size_t)MM * DD];
__device__ __align__(16) __half g_a16[(size_t)MM * DD];
__device__ __align__(16) __half g_q16[(size_t)MM * DD];   // pre-scaled by 0.125*log2(e)
__device__ __align__(16) __half g_k16[(size_t)MM * DD];
__device__ __align__(16) __half g_v16[(size_t)MM * DD];
__device__ __align__(16) __half g_w16[4][(size_t)DD * DD];   // Wq,Wk,Wv,Wp

// ---------------------------------------------------------------------------
// fp32 -> fp16 converts
// ---------------------------------------------------------------------------
__global__ void cvt_x(const float* __restrict__ src, int n4)
{
    int i = blockIdx.x * blockDim.x + threadIdx.x;
    if (i >= n4) return;
    float4 v = ((const float4*)src)[i];
    *(__half2*)&g_x16[4 * (size_t)i]     = __floats2half2_rn(v.x, v.y);
    *(__half2*)&g_x16[4 * (size_t)i + 2] = __floats2half2_rn(v.z, v.w);
}

__global__ void cvt_w(const float* __restrict__ w0, const float* __restrict__ w1,
                      const float* __restrict__ w2, const float* __restrict__ w3,
                      int n4)
{
    int i = blockIdx.x * blockDim.x + threadIdx.x;
    if (i >= n4) return;
    int s = blockIdx.y;
    const float* src = (s == 0) ? w0 : (s == 1) ? w1 : (s == 2) ? w2 : w3;
    float4 v = ((const float4*)src)[i];
    __half* H = g_w16[s];
    *(__half2*)&H[4 * (size_t)i]     = __floats2half2_rn(v.x, v.y);
    *(__half2*)&H[4 * (size_t)i + 2] = __floats2half2_rn(v.z, v.w);
}

// ---------------------------------------------------------------------------
// MMA / cp.async helpers
// ---------------------------------------------------------------------------
__device__ __forceinline__ uint32_t smem_u32(const void* p) {
    return (uint32_t)__cvta_generic_to_shared(p);
}
__device__ __forceinline__ void ldm_x4(uint32_t addr, uint32_t* r) {
    asm volatile("ldmatrix.sync.aligned.m8n8.x4.shared.b16 {%0,%1,%2,%3}, [%4];"
                 : "=r"(r[0]), "=r"(r[1]), "=r"(r[2]), "=r"(r[3]) : "r"(addr));
}
__device__ __forceinline__ void ldm_x4_t(uint32_t addr, uint32_t* r) {
    asm volatile("ldmatrix.sync.aligned.m8n8.x4.trans.shared.b16 {%0,%1,%2,%3}, [%4];"
                 : "=r"(r[0]), "=r"(r[1]), "=r"(r[2]), "=r"(r[3]) : "r"(addr));
}
__device__ __forceinline__ void mma_f16(float* c, const uint32_t* a, uint32_t b0, uint32_t b1) {
    asm volatile("mma.sync.aligned.m16n8k16.row.col.f32.f16.f16.f32 "
                 "{%0,%1,%2,%3}, {%4,%5,%6,%7}, {%8,%9}, {%0,%1,%2,%3};"
                 : "+f"(c[0]), "+f"(c[1]), "+f"(c[2]), "+f"(c[3])
                 : "r"(a[0]), "r"(a[1]), "r"(a[2]), "r"(a[3]), "r"(b0), "r"(b1));
}
__device__ __forceinline__ void cp16(uint32_t dst, const void* src) {
    asm volatile("cp.async.cg.shared.global [%0], [%1], 16;" :: "r"(dst), "l"(src));
}
__device__ __forceinline__ void cp_commit() {
    asm volatile("cp.async.commit_group;");
}
template <int N>
__device__ __forceinline__ void cp_wait() {
    asm volatile("cp.async.wait_group %0;" :: "n"(N));
}

// ---------------------------------------------------------------------------
// fp16 NT GEMM, fp32 accumulate. Block 128x128, BK=64, 2-stage cp.async,
// ONE __syncthreads per K-iter, 2 CTAs/SM.
// mode 0: fp32 out + bias.  mode 1: fused QKV epilogue (fp16, Q*0.125*log2e)
// ---------------------------------------------------------------------------
#define GBK 64
#define GSST 72
#define GMAT (128 * GSST)
#define GSTAGE (2 * GMAT)
#define GEMM_SMEM (2 * GSTAGE * 2)   // 73728 bytes

__global__ __launch_bounds__(256, 2)
void gemm_nt_f16(int aSel, int wSel, const float* __restrict__ bias,
                 float* __restrict__ Cout, int mode, int M, int N, int K)
{
    const __half* A = aSel ? g_a16 : g_x16;
    const __half* W = g_w16[wSel];

    extern __shared__ __half dsm[];

    const int tid  = threadIdx.x;
    const int warp = tid >> 5, lane = tid & 31;
    const int wm = warp >> 1, wn = warp & 1;
    const int m0 = blockIdx.y * 128, n0 = blockIdx.x * 128;

    // load mapping: row = tid>>1, 32-half chunk = (tid&1)*32, 4x cp16 each matrix
    const int lrow = tid >> 1;
    const int lcol = (tid & 1) * 32;
    const size_t gA = (size_t)(m0 + lrow) * K + lcol;
    const size_t gW = (size_t)(n0 + lrow) * K + lcol;
    const int soff = lrow * GSST + lcol;

    const int KITERS = K / GBK;   // 16

#define G_ISSUE(it, st)                                                        \
    do {                                                                       \
        const int _k0 = (it) * GBK;                                            \
        __half* _s = dsm + (st) * GSTAGE;                                      \
        cp16(smem_u32(_s + soff),              A + gA + _k0);                  \
        cp16(smem_u32(_s + soff + 8),          A + gA + _k0 + 8);              \
        cp16(smem_u32(_s + soff + 16),         A + gA + _k0 + 16);             \
        cp16(smem_u32(_s + soff + 24),         A + gA + _k0 + 24);             \
        cp16(smem_u32(_s + GMAT + soff),       W + gW + _k0);                  \
        cp16(smem_u32(_s + GMAT + soff + 8),   W + gW + _k0 + 8);              \
        cp16(smem_u32(_s + GMAT + soff + 16),  W + gW + _k0 + 16);             \
        cp16(smem_u32(_s + GMAT + soff + 24),  W + gW + _k0 + 24);             \
    } while (0)

    float acc[2][8][4];
#pragma unroll
    for (int i = 0; i < 2; ++i)
#pragma unroll
        for (int j = 0; j < 8; ++j)
#pragma unroll
            for (int t = 0; t < 4; ++t) acc[i][j][t] = 0.f;

    G_ISSUE(0, 0);
    cp_commit();

    for (int it = 0; it < KITERS; ++it) {
        cp_wait<0>();            // stage 'it' landed (only outstanding group)
        __syncthreads();         // all warps done consuming stage 'it-1'
        if (it + 1 < KITERS) {
            G_ISSUE(it + 1, (it + 1) & 1);
            cp_commit();
        }

        const __half* sA = dsm + (it & 1) * GSTAGE;
        const __half* sW = sA + GMAT;

#pragma unroll
        for (int ks = 0; ks < GBK; ks += 16) {
            uint32_t aF[2][4], bF[4][4];
            const int arow = wm * 32 + (lane & 15);
            const int acol = ks + ((lane >> 4) << 3);
#pragma unroll
            for (int mt = 0; mt < 2; ++mt)
                ldm_x4(smem_u32(&sA[(arow + mt * 16) * GSST + acol]), aF[mt]);
            const int brow = wn * 64 + ((lane >> 4) << 3) + (lane & 7);
            const int bcol = ks + ((lane >> 3) & 1) * 8;
#pragma unroll
            for (int nn = 0; nn < 4; ++nn)
                ldm_x4(smem_u32(&sW[(brow + nn * 16) * GSST + bcol]), bF[nn]);
#pragma unroll
            for (int mt = 0; mt < 2; ++mt)
#pragma unroll
                for (int nt = 0; nt < 8; ++nt) {
                    const int p = nt >> 1, q = (nt & 1) * 2;
                    mma_f16(acc[mt][nt], aF[mt], bF[p][q], bF[p][q + 1]);
                }
        }
    }
#undef G_ISSUE

#pragma unroll
    for (int mt = 0; mt < 2; ++mt) {
#pragma unroll
        for (int nt = 0; nt < 8; ++nt) {
            const int m = m0 + wm * 32 + mt * 16 + (lane >> 2);
            const int n = n0 + wn * 64 + nt * 8 + (lane & 3) * 2;
            if (mode == 0) {
                float b0 = bias[n], b1 = bias[n + 1];
                *(float2*)&Cout[(size_t)m * N + n] =
                    make_float2(acc[mt][nt][0] + b0, acc[mt][nt][1] + b1);
                *(float2*)&Cout[(size_t)(m + 8) * N + n] =
                    make_float2(acc[mt][nt][2] + b0, acc[mt][nt][3] + b1);
            } else {
                const int arr = n >> 10;
                const int nc  = n & 1023;
                const float s = (arr == 0) ? (0.125f * LOG2E) : 1.f;
                __half* H = (arr == 0) ? g_q16 : (arr == 1) ? g_k16 : g_v16;
                __half2 v0 = __floats2half2_rn(acc[mt][nt][0] * s, acc[mt][nt][1] * s);
                __half2 v1 = __floats2half2_rn(acc[mt][nt][2] * s, acc[mt][nt][3] * s);
                *(__half2*)&H[(size_t)m * DD + nc]       = v0;
                *(__half2*)&H[(size_t)(m + 8) * DD + nc] = v1;
            }
        }
    }
}

// ---------------------------------------------------------------------------
// fp16 causal flash attention, cp.async double-buffered K/V, base-2 softmax.
// Block: 128 q rows of one (b,h), 256 threads = 8 warps, 16 q rows/warp.
// ---------------------------------------------------------------------------
__global__ __launch_bounds__(256, 2)
void flash_attn_f16()
{
    const int qb = gridDim.x - 1 - blockIdx.x;   // heavy blocks first
    const int h  = blockIdx.y;
    const int b  = blockIdx.z;
    const int tid  = threadIdx.x;
    const int warp = tid >> 5, lane = tid & 31;

    __shared__ __align__(16) __half smQ[128 * 72];
    __shared__ __align__(16) __half smKV[2][128 * 72];   // [buf][K rows 0..63 | V rows 64..127]

    const int q0 = qb * 128;
    const int qbase = q0 + warp * 16;
    const int nk = q0 + 128;

    // prologue: issue cp.async for KV tile 0 immediately
    {
        const size_t gk = ((size_t)(b * TT)) * DD + h * HD;
#pragma unroll
        for (int i = 0; i < 4; ++i) {
            int idx = tid + i * 256;       // 0..1023 cp16
            int mat = idx >> 9;            // 0=K, 1=V
            int w   = idx & 511;
            int row = w >> 3;
            int col = (w & 7) * 8;
            const __half* src = mat ? g_v16 : g_k16;
            cp16(smem_u32(&smKV[0][(mat * 64 + row) * 72 + col]),
                 &src[gk + (size_t)row * DD + col]);
        }
        cp_commit();
    }

    // stage Q tile [128 x 64] (plain loads; overlaps with the cp.async above)
    {
        const size_t g0 = ((size_t)(b * TT + q0)) * DD + h * HD;
#pragma unroll
        for (int i = 0; i < 4; ++i) {
            int idx = tid + i * 256;
            int row = idx >> 3;
            int col = (idx & 7) * 8;
            *(int4*)&smQ[row * 72 + col] =
                *(const int4*)&g_q16[g0 + (size_t)row * DD + col];
        }
    }
    __syncthreads();

    uint32_t aQ[4][4];
    {
        const int arow = warp * 16 + (lane & 15);
#pragma unroll
        for (int c = 0; c < 4; ++c) {
            const int acol = c * 16 + ((lane >> 4) << 3);
            ldm_x4(smem_u32(&smQ[arow * 72 + acol]), aQ[c]);
        }
    }

    float oacc[8][4];
#pragma unroll
    for (int nt = 0; nt < 8; ++nt)
#pragma unroll
        for (int t = 0; t < 4; ++t) oacc[nt][t] = 0.f;
    float m0 = 0.f, m1 = 0.f, l0 = 0.f, l1 = 0.f;

    const int r0i = qbase + (lane >> 2);
    const int r1i = r0i + 8;

    for (int kt = 0, idx0 = 0; kt < nk; kt += 64, ++idx0) {
        cp_wait<0>();            // KV tile 'idx0' landed
        __syncthreads();         // everyone done consuming buf (idx0+1)&1

        // overlap: issue next KV tile into the other buffer
        if (kt + 64 < nk) {
            const size_t gk = ((size_t)(b * TT + kt + 64)) * DD + h * HD;
            __half* dst = smKV[(idx0 + 1) & 1];
#pragma unroll
            for (int i = 0; i < 4; ++i) {
                int idx = tid + i * 256;
                int mat = idx >> 9;
                int w   = idx & 511;
                int row = w >> 3;
                int col = (w & 7) * 8;
                const __half* src = mat ? g_v16 : g_k16;
                cp16(smem_u32(&dst[(mat * 64 + row) * 72 + col]),
                     &src[gk + (size_t)row * DD + col]);
            }
            cp_commit();
        }

        if (kt <= qbase) {
            const __half* sm = smKV[idx0 & 1];

            // S = Q K^T  (logits already in base-2 domain via Q pre-scale)
            float sacc[8][4];
#pragma unroll
            for (int nt = 0; nt < 8; ++nt)
#pragma unroll
                for (int t = 0; t < 4; ++t) sacc[nt][t] = 0.f;

            const int brow = ((lane >> 4) << 3) + (lane & 7);
#pragma unroll
            for (int c = 0; c < 4; ++c) {
                uint32_t bK[4][4];
                const int bcol = c * 16 + ((lane >> 3) & 1) * 8;
#pragma unroll
                for (int p = 0; p < 4; ++p)
                    ldm_x4(smem_u32(&sm[(p * 16 + brow) * 72 + bcol]), bK[p]);
#pragma unroll
                for (int nt = 0; nt < 8; ++nt) {
                    const int p = nt >> 1, q = (nt & 1) * 2;
                    mma_f16(sacc[nt], aQ[c], bK[p][q], bK[p][q + 1]);
                }
            }

            // causal mask on diagonal tiles
            if (kt + 63 > qbase) {
#pragma unroll
                for (int nt = 0; nt < 8; ++nt) {
                    const int cb = kt + nt * 8 + (lane & 3) * 2;
                    if (cb     > r0i) sacc[nt][0] = -1e30f;
                    if (cb + 1 > r0i) sacc[nt][1] = -1e30f;
                    if (cb     > r1i) sacc[nt][2] = -1e30f;
                    if (cb + 1 > r1i) sacc[nt][3] = -1e30f;
                }
            }

            // online softmax (base-2)
            float tm0 = -1e30f, tm1 = -1e30f;
#pragma unroll
            for (int nt = 0; nt < 8; ++nt) {
                tm0 = fmaxf(tm0, fmaxf(sacc[nt][0], sacc[nt][1]));
                tm1 = fmaxf(tm1, fmaxf(sacc[nt][2], sacc[nt][3]));
            }
            tm0 = fmaxf(tm0, __shfl_xor_sync(0xffffffffu, tm0, 1));
            tm0 = fmaxf(tm0, __shfl_xor_sync(0xffffffffu, tm0, 2));
            tm1 = fmaxf(tm1, __shfl_xor_sync(0xffffffffu, tm1, 1));
            tm1 = fmaxf(tm1, __shfl_xor_sync(0xffffffffu, tm1, 2));

            const float mn0 = fmaxf(m0, tm0), mn1 = fmaxf(m1, tm1);
            const float c0 = exp2f(m0 - mn0), c1 = exp2f(m1 - mn1);
            m0 = mn0; m1 = mn1;
            l0 *= c0;  l1 *= c1;
#pragma unroll
            for (int nt = 0; nt < 8; ++nt) {
                oacc[nt][0] *= c0; oacc[nt][1] *= c0;
                oacc[nt][2] *= c1; oacc[nt][3] *= c1;
            }

            uint32_t aP[4][4];
            float ls0 = 0.f, ls1 = 0.f;
#pragma unroll
            for (int nt = 0; nt < 8; ++nt) {
                const float p0 = exp2f(sacc[nt][0] - mn0);
                const float p1 = exp2f(sacc[nt][1] - mn0);
                const float p2 = exp2f(sacc[nt][2] - mn1);
                const float p3 = exp2f(sacc[nt][3] - mn1);
                ls0 += p0 + p1;  ls1 += p2 + p3;
                const int c = nt >> 1, rr = (nt & 1) * 2;
                __half2 h01 = __floats2half2_rn(p0, p1);
                __half2 h23 = __floats2half2_rn(p2, p3);
                aP[c][rr]     = reinterpret_cast<uint32_t&>(h01);
                aP[c][rr + 1] = reinterpret_cast<uint32_t&>(h23);
            }
            l0 += ls0;  l1 += ls1;

            // O += P V  (V rows 64..127 of buffer, via ldmatrix.trans)
#pragma unroll
            for (int c = 0; c < 4; ++c) {
                uint32_t bV[8][2];
                const int vrow = c * 16 + ((lane >> 3) & 1) * 8 + (lane & 7);
                const int vcol0 = (lane >> 4) << 3;
#pragma unroll
                for (int pr = 0; pr < 4; ++pr) {
                    uint32_t r[4];
                    ldm_x4_t(smem_u32(&sm[(64 + vrow) * 72 + 16 * pr + vcol0]), r);
                    bV[2 * pr][0] = r[0]; bV[2 * pr][1] = r[1];
                    bV[2 * pr + 1][0] = r[2]; bV[2 * pr + 1][1] = r[3];
                }
#pragma unroll
                for (int nt = 0; nt < 8; ++nt)
                    mma_f16(oacc[nt], aP[c], bV[nt][0], bV[nt][1]);
            }
        }
    }

    // finalize: normalize, emit fp16 attn-out
    l0 += __shfl_xor_sync(0xffffffffu, l0, 1);
    l0 += __shfl_xor_sync(0xffffffffu, l0, 2);
    l1 += __shfl_xor_sync(0xffffffffu, l1, 1);
    l1 += __shfl_xor_sync(0xffffffffu, l1, 2);
    const float inv0 = 1.f / l0, inv1 = 1.f / l1;

#pragma unroll
    for (int nt = 0; nt < 8; ++nt) {
        const int col = h * HD + nt * 8 + (lane & 3) * 2;
        const size_t o0 = ((size_t)(b * TT + r0i)) * DD + col;
        const size_t o1 = ((size_t)(b * TT + r1i)) * DD + col;
        *(__half2*)&g_a16[o0] = __floats2half2_rn(oacc[nt][0] * inv0, oacc[nt][1] * inv0);
        *(__half2*)&g_a16[o1] = __floats2half2_rn(oacc[nt][2] * inv1, oacc[nt][3] * inv1);
    }
}

// ---------------------------------------------------------------------------
// Launch: inputs per metadata order: x, Wk, Wq, Wv, Wp, bp
// ---------------------------------------------------------------------------
extern "C" void kernel_launch(void* const* d_in, const int* in_sizes, int n_in,
                              void* d_out, int out_size)
{
    const float* x  = (const float*)d_in[0];
    const float* Wk = (const float*)d_in[1];
    const float* Wq = (const float*)d_in[2];
    const float* Wv = (const float*)d_in[3];
    const float* Wp = (const float*)d_in[4];
    const float* bp = (const float*)d_in[5];
    float* out = (float*)d_out;

    cudaFuncSetAttribute(gemm_nt_f16, cudaFuncAttributeMaxDynamicSharedMemorySize,
                         GEMM_SMEM);

    // converts: x, then all 4 weights (slot order: Wq, Wk, Wv, Wp)
    {
        int n4 = MM * DD / 4;
        cvt_x<<<(n4 + 255) / 256, 256>>>(x, n4);
        int w4 = DD * DD / 4;
        dim3 wg((w4 + 255) / 256, 4);
        cvt_w<<<wg, 256>>>(Wq, Wk, Wv, Wp, w4);
    }

    // fused QKV projection: N = 3072 (weight slots 0..2 contiguous)
    dim3 qkvGrid(3 * DD / 128, MM / 128);   // 24 x 64
    gemm_nt_f16<<<qkvGrid, 256, GEMM_SMEM>>>(0, 0, nullptr, nullptr, 1, MM, 3 * DD, DD);

    // fp16 causal flash attention -> g_a16
    dim3 fGrid(TT / 128, HH, BB);           // 16 x 16 x 4
    flash_attn_f16<<<fGrid, 256>>>();

    // output projection with bias -> d_out (fp32)
    dim3 oGrid(DD / 128, MM / 128);         // 8 x 64
    gemm_nt_f16<<<oGrid, 256, GEMM_SMEM>>>(1, 3, bp, out, 0, MM, DD, DD);
}